// round 8
// baseline (speedup 1.0000x reference)
#include <cuda_runtime.h>
#include <cuda_bf16.h>
#include <cstdint>
#include <cstddef>
#include <math.h>

// Problem constants
#define BATCH 8
#define CCH   256
#define HW    16384
#define HID   512
#define CHUNK 64
#define NG    (HW / CHUNK)

// Generic GEMM tiling: 128x128 CTA, 4 warps x (64x64), BK=32, 4-stage pipeline
#define BM 128
#define BN 128
#define BK 32
#define ASTRIDE 40
#define BSTRIDE 136
#define ASZB (BM * ASTRIDE * 2)     // 10240 B per A stage
#define BSZB (BK * BSTRIDE * 2)     // 8704 B per B stage
#define GSTG 4
#define GE_SMEM (GSTG * (ASZB + BSZB))   // 75776 B

// Fused proj+LN2: M=256, N=64, BK=32, 3-stage
#define PASTR 40
#define PBSTR 72
#define PASZB (256 * PASTR * 2)     // 20480 B
#define PBSZB (32 * PBSTR * 2)      // 4608 B
#define PSTG 3
#define PJ_RED (PSTG * (PASZB + PBSZB))          // 75264
#define PJ_SMEM (PJ_RED + 1024 + 1024 + 256 + 256) // 77824 B

// attention smem layout (bf16 elems), row stride 72
#define ATS 72
#define AT_QV 0
#define AT_K  (256 * ATS)
#define AT_P  (512 * ATS)
#define AT_ELEMS (512 * ATS + 64 * ATS)
#define AT_SMEM_BYTES (AT_ELEMS * 2)

// LN smem
#define LN_SMEM_BYTES (256 * 65 * 4 + 128 * 4)

// ---------------- scratch ----------------
__device__ __nv_bfloat16 g_xln [BATCH * CCH * HW];
__device__ __nv_bfloat16 g_qkv [BATCH * 3 * CCH * HW];
__device__ __nv_bfloat16 g_attn[BATCH * CCH * HW];
__device__ float         g_x2  [BATCH * CCH * HW];
__device__ __nv_bfloat16 g_h1  [BATCH * HID * HW];
__device__ __nv_bfloat16 g_h2  [BATCH * HID * HW];
__device__ __nv_bfloat16 g_wbf [768*256 + 256*256 + 512*256 + 256*512];

__device__ __forceinline__ float gelu_f(float v) {
    return 0.5f * v * (1.0f + erff(v * 0.70710678118654752f));
}

union BF2U { __nv_bfloat162 h; unsigned int u; };
__device__ __forceinline__ unsigned int pack_bf2(float a, float b) {
    BF2U t; t.h = __floats2bfloat162_rn(a, b); return t.u;
}

// ---------------- helpers ----------------
__device__ __forceinline__ void ldsm_x4(unsigned int* r, unsigned int addr) {
    asm volatile("ldmatrix.sync.aligned.m8n8.x4.shared.b16 {%0,%1,%2,%3}, [%4];"
                 : "=r"(r[0]), "=r"(r[1]), "=r"(r[2]), "=r"(r[3]) : "r"(addr));
}
__device__ __forceinline__ void ldsm_x4_t(unsigned int* r, unsigned int addr) {
    asm volatile("ldmatrix.sync.aligned.m8n8.x4.trans.shared.b16 {%0,%1,%2,%3}, [%4];"
                 : "=r"(r[0]), "=r"(r[1]), "=r"(r[2]), "=r"(r[3]) : "r"(addr));
}
__device__ __forceinline__ void mma_bf16(float* d, const unsigned int* a, const unsigned int* b) {
    asm volatile("mma.sync.aligned.m16n8k16.row.col.f32.bf16.bf16.f32 "
                 "{%0,%1,%2,%3}, {%4,%5,%6,%7}, {%8,%9}, {%0,%1,%2,%3};"
                 : "+f"(d[0]), "+f"(d[1]), "+f"(d[2]), "+f"(d[3])
                 : "r"(a[0]), "r"(a[1]), "r"(a[2]), "r"(a[3]), "r"(b[0]), "r"(b[1]));
}
__device__ __forceinline__ void cp_async16(unsigned int dst, const void* src) {
    asm volatile("cp.async.cg.shared.global [%0], [%1], 16;" :: "r"(dst), "l"(src));
}
__device__ __forceinline__ void cp_commit() {
    asm volatile("cp.async.commit_group;" ::: "memory");
}
__device__ __forceinline__ void cp_wait0() {
    asm volatile("cp.async.wait_group 0;" ::: "memory");
}
__device__ __forceinline__ void cp_wait1() {
    asm volatile("cp.async.wait_group 1;" ::: "memory");
}
__device__ __forceinline__ void cp_wait2() {
    asm volatile("cp.async.wait_group 2;" ::: "memory");
}

// ---------------- merged weight fp32 -> bf16 ----------------
__global__ void cvt_all_kernel(const float* __restrict__ s0, const float* __restrict__ s1,
                               const float* __restrict__ s2, const float* __restrict__ s3,
                               __nv_bfloat16* __restrict__ dst)
{
    int i = blockIdx.x * 256 + threadIdx.x;
    const float* s; int off;
    if (i < 196608)      { s = s0; off = i; }
    else if (i < 262144) { s = s1; off = i - 196608; }
    else if (i < 393216) { s = s2; off = i - 262144; }
    else                 { s = s3; off = i - 393216; }
    dst[i] = __float2bfloat16(s[off]);
}

// ---------------- single-pass LayerNorm (LN1) ----------------
__global__ __launch_bounds__(256)
void ln_kernel(const float* __restrict__ in,
               const float* __restrict__ scale,
               const float* __restrict__ bias,
               __nv_bfloat16* __restrict__ out)
{
    extern __shared__ float lns[];
    float* ts  = lns;
    float* mus = lns + 256 * 65;
    float* rs  = mus + 64;

    int bp = blockIdx.x;
    int b  = bp >> 8;
    int p0 = (bp & 255) * 64;
    int tid = threadIdx.x;
    const float* ip = in + (size_t)b * CCH * HW + p0;

#pragma unroll
    for (int k = 0; k < 64; k++) {
        int e = k * 256 + tid;
        int c = e >> 6, p = e & 63;
        ts[c * 65 + p] = ip[(size_t)c * HW + p];
    }
    __syncthreads();

    {
        int tq = tid & 3, pp = tid >> 2;
        float s = 0.f, s2 = 0.f;
#pragma unroll 16
        for (int j = 0; j < 64; j++) {
            float v = ts[(tq + 4 * j) * 65 + pp];
            s += v; s2 += v * v;
        }
        s  += __shfl_xor_sync(0xffffffffu, s, 1);
        s  += __shfl_xor_sync(0xffffffffu, s, 2);
        s2 += __shfl_xor_sync(0xffffffffu, s2, 1);
        s2 += __shfl_xor_sync(0xffffffffu, s2, 2);
        float mu  = s * (1.0f / CCH);
        float var = s2 * (1.0f / CCH) - mu * mu;
        if (tq == 0) { mus[pp] = mu; rs[pp] = rsqrtf(var + 1e-5f); }
    }
    __syncthreads();

    __nv_bfloat16* op = out + (size_t)b * CCH * HW + p0;
#pragma unroll
    for (int k = 0; k < 64; k++) {
        int e = k * 256 + tid;
        int c = e >> 6, p = e & 63;
        float v = ts[c * 65 + p];
        op[(size_t)c * HW + p] = __float2bfloat16((v - mus[p]) * rs[p] * scale[c] + bias[c]);
    }
}

// ---------------- bf16 mma.sync GEMM: 128x128 CTA, 4 warps x 64x64, 4-stage ----
// epi: 0 = +bias -> bf16 ; 1 = +bias + Res(fp32) -> fp32 ; 2 = gelu(+bias) -> bf16
__global__ __launch_bounds__(128)
void gemm_bf16_kernel(const __nv_bfloat16* __restrict__ A,
                      const __nv_bfloat16* __restrict__ Bact,
                      const float* __restrict__ bias,
                      const float* __restrict__ Res,
                      void* __restrict__ Cout,
                      int K, long strideB, long strideC, int epi)
{
    extern __shared__ __nv_bfloat16 gsm[];
    unsigned int as_base = (unsigned int)__cvta_generic_to_shared(gsm);
    unsigned int bs_base = as_base + GSTG * ASZB;

    int tid = threadIdx.x;
    int m0 = blockIdx.y * BM;
    int p0 = blockIdx.x * BN;
    int b  = blockIdx.z;
    const __nv_bfloat16* Bp = Bact + (size_t)b * strideB + p0;
    const __nv_bfloat16* Ap = A + (size_t)m0 * K;

    // A tile: 128 rows x 32 bf16 = 512 vec16; 4 per thread (rows tid>>2 + i*32)
    int ar0 = tid >> 2, ac = (tid & 3) * 8;
    // B tile: 32 rows x 128 bf16 = 512 vec16; 4 per thread (rows tid>>4 + i*8)
    int br0 = tid >> 4, bc = (tid & 15) * 8;

    int nk = K >> 5;

    // prologue: stages 0..GSTG-2
#pragma unroll
    for (int s = 0; s < GSTG - 1; s++) {
        if (s < nk) {
            int k0 = s * BK;
            unsigned int ao = as_base + s * ASZB;
            unsigned int bo = bs_base + s * BSZB;
#pragma unroll
            for (int i = 0; i < 4; i++) {
                int r = ar0 + i * 32;
                cp_async16(ao + (r * ASTRIDE + ac) * 2, Ap + (size_t)r * K + k0 + ac);
            }
#pragma unroll
            for (int i = 0; i < 4; i++) {
                int r = br0 + i * 8;
                cp_async16(bo + (r * BSTRIDE + bc) * 2, Bp + (size_t)(k0 + r) * HW + bc);
            }
        }
        cp_commit();
    }

    int warp = tid >> 5, lane = tid & 31;
    int wm = warp >> 1;          // 0..1
    int wn = warp & 1;           // 0..1

    float acc[4][8][4];
#pragma unroll
    for (int i = 0; i < 4; i++)
#pragma unroll
        for (int j = 0; j < 8; j++)
#pragma unroll
            for (int q = 0; q < 4; q++) acc[i][j][q] = 0.f;

    int a_row = wm * 64 + (lane & 15);
    int a_col = (lane >> 4) * 8;
    int b_row = (lane & 15);
    int b_col = wn * 64 + (lane >> 4) * 8;

    for (int kt = 0; kt < nk; kt++) {
        cp_wait2();
        __syncthreads();

        int ps = kt + GSTG - 1;
        if (ps < nk) {
            int k0 = ps * BK;
            unsigned int ao = as_base + (ps & (GSTG - 1)) * ASZB;
            unsigned int bo = bs_base + (ps & (GSTG - 1)) * BSZB;
#pragma unroll
            for (int i = 0; i < 4; i++) {
                int r = ar0 + i * 32;
                cp_async16(ao + (r * ASTRIDE + ac) * 2, Ap + (size_t)r * K + k0 + ac);
            }
#pragma unroll
            for (int i = 0; i < 4; i++) {
                int r = br0 + i * 8;
                cp_async16(bo + (r * BSTRIDE + bc) * 2, Bp + (size_t)(k0 + r) * HW + bc);
            }
        }
        cp_commit();

        unsigned int abase = as_base + (kt & (GSTG - 1)) * ASZB;
        unsigned int bbase = bs_base + (kt & (GSTG - 1)) * BSZB;
#pragma unroll
        for (int kk = 0; kk < 2; kk++) {
            unsigned int af[4][4];
            unsigned int bfr[4][4];
#pragma unroll
            for (int i = 0; i < 4; i++)
                ldsm_x4(af[i], abase + (((a_row + i * 16) * ASTRIDE) + a_col + kk * 16) * 2);
#pragma unroll
            for (int j = 0; j < 4; j++)
                ldsm_x4_t(bfr[j], bbase + (((b_row + kk * 16) * BSTRIDE) + b_col + j * 16) * 2);
#pragma unroll
            for (int i = 0; i < 4; i++)
#pragma unroll
                for (int jn = 0; jn < 8; jn++)
                    mma_bf16(acc[i][jn], af[i], &bfr[jn >> 1][(jn & 1) * 2]);
        }
    }

    // epilogue
    int l4 = lane >> 2, l2 = (lane & 3) * 2;
#pragma unroll
    for (int i = 0; i < 4; i++) {
        int r0 = m0 + wm * 64 + i * 16 + l4;
        int r1 = r0 + 8;
        float bv0 = bias[r0], bv1 = bias[r1];
#pragma unroll
        for (int jn = 0; jn < 8; jn++) {
            int col = p0 + wn * 64 + jn * 8 + l2;
            size_t off0 = (size_t)b * strideC + (size_t)r0 * HW + col;
            size_t off1 = (size_t)b * strideC + (size_t)r1 * HW + col;
            float v0 = acc[i][jn][0] + bv0;
            float v1 = acc[i][jn][1] + bv0;
            float v2 = acc[i][jn][2] + bv1;
            float v3 = acc[i][jn][3] + bv1;
            if (epi == 1) {
                float* Cf = (float*)Cout;
                float2 q0 = *(const float2*)(Res + off0);
                float2 q1 = *(const float2*)(Res + off1);
                *(float2*)(Cf + off0) = make_float2(v0 + q0.x, v1 + q0.y);
                *(float2*)(Cf + off1) = make_float2(v2 + q1.x, v3 + q1.y);
            } else {
                if (epi == 2) {
                    v0 = gelu_f(v0); v1 = gelu_f(v1);
                    v2 = gelu_f(v2); v3 = gelu_f(v3);
                }
                __nv_bfloat16* Cb = (__nv_bfloat16*)Cout;
                *(unsigned int*)(Cb + off0) = pack_bf2(v0, v1);
                *(unsigned int*)(Cb + off1) = pack_bf2(v2, v3);
            }
        }
    }
}

// ---------------- fused proj GEMM + residual + LN2 (unchanged from R7) ----------------
__global__ __launch_bounds__(256, 2)
void proj_ln2_kernel(const __nv_bfloat16* __restrict__ Wp,
                     const __nv_bfloat16* __restrict__ Bact,
                     const float* __restrict__ bias,
                     const float* __restrict__ Resx,
                     const float* __restrict__ ln_s,
                     const float* __restrict__ ln_b,
                     float* __restrict__ X2,
                     __nv_bfloat16* __restrict__ Xln)
{
    extern __shared__ __nv_bfloat16 psm[];
    unsigned int as_base = (unsigned int)__cvta_generic_to_shared(psm);
    unsigned int bs_base = as_base + PSTG * PASZB;
    float* pm  = (float*)((char*)psm + PJ_RED);
    float* pq  = pm + 4 * 64;
    float* msm = pq + 4 * 64;
    float* rsm = msm + 64;

    int tid = threadIdx.x;
    int p0 = blockIdx.x * 64;
    int b  = blockIdx.z;
    const __nv_bfloat16* Bp = Bact + (size_t)b * CCH * HW + p0;

    int ar = tid >> 2, ac = (tid & 3) * 8;
    int br = tid >> 3, bc = (tid & 7) * 8;

#pragma unroll
    for (int s = 0; s < PSTG - 1; s++) {
        int k0 = s * 32;
        unsigned int ao = as_base + s * PASZB;
        unsigned int bo = bs_base + s * PBSZB;
#pragma unroll
        for (int i = 0; i < 4; i++) {
            int r = ar + i * 64;
            cp_async16(ao + (r * PASTR + ac) * 2, Wp + (size_t)r * 256 + k0 + ac);
        }
        cp_async16(bo + (br * PBSTR + bc) * 2, Bp + (size_t)(k0 + br) * HW + bc);
        cp_commit();
    }

    int warp = tid >> 5, lane = tid & 31;
    int wm = warp >> 1;
    int wn = warp & 1;

    float acc[4][4][4];
#pragma unroll
    for (int i = 0; i < 4; i++)
#pragma unroll
        for (int j = 0; j < 4; j++)
#pragma unroll
            for (int q = 0; q < 4; q++) acc[i][j][q] = 0.f;

    int a_row = wm * 64 + (lane & 15);
    int a_col = (lane >> 4) * 8;
    int b_row = (lane & 15);
    int b_col = wn * 32 + (lane >> 4) * 8;

    for (int kt = 0; kt < 8; kt++) {
        cp_wait1();
        __syncthreads();

        int ps = kt + PSTG - 1;
        if (ps < 8) {
            int k0 = ps * 32;
            unsigned int ao = as_base + (ps % PSTG) * PASZB;
            unsigned int bo = bs_base + (ps % PSTG) * PBSZB;
#pragma unroll
            for (int i = 0; i < 4; i++) {
                int r = ar + i * 64;
                cp_async16(ao + (r * PASTR + ac) * 2, Wp + (size_t)r * 256 + k0 + ac);
            }
            cp_async16(bo + (br * PBSTR + bc) * 2, Bp + (size_t)(k0 + br) * HW + bc);
        }
        cp_commit();

        unsigned int abase = as_base + (kt % PSTG) * PASZB;
        unsigned int bbase = bs_base + (kt % PSTG) * PBSZB;
#pragma unroll
        for (int kk = 0; kk < 2; kk++) {
            unsigned int af[4][4];
            unsigned int bfr[2][4];
#pragma unroll
            for (int i = 0; i < 4; i++)
                ldsm_x4(af[i], abase + (((a_row + i * 16) * PASTR) + a_col + kk * 16) * 2);
#pragma unroll
            for (int j = 0; j < 2; j++)
                ldsm_x4_t(bfr[j], bbase + (((b_row + kk * 16) * PBSTR) + b_col + j * 16) * 2);
#pragma unroll
            for (int i = 0; i < 4; i++)
#pragma unroll
                for (int jn = 0; jn < 4; jn++)
                    mma_bf16(acc[i][jn], af[i], &bfr[jn >> 1][(jn & 1) * 2]);
        }
    }

    int l4 = lane >> 2, l2 = (lane & 3) * 2;
    float s0[8], s1[8];
#pragma unroll
    for (int u = 0; u < 8; u++) { s0[u] = 0.f; s1[u] = 0.f; }

#pragma unroll
    for (int i = 0; i < 4; i++) {
        int r0 = wm * 64 + i * 16 + l4;
        int r1 = r0 + 8;
        float bv0 = bias[r0], bv1 = bias[r1];
#pragma unroll
        for (int jn = 0; jn < 4; jn++) {
            int col = p0 + wn * 32 + jn * 8 + l2;
            size_t off0 = (size_t)b * CCH * HW + (size_t)r0 * HW + col;
            size_t off1 = (size_t)b * CCH * HW + (size_t)r1 * HW + col;
            float2 q0 = *(const float2*)(Resx + off0);
            float2 q1 = *(const float2*)(Resx + off1);
            float v0 = acc[i][jn][0] + bv0 + q0.x;
            float v1 = acc[i][jn][1] + bv0 + q0.y;
            float v2 = acc[i][jn][2] + bv1 + q1.x;
            float v3 = acc[i][jn][3] + bv1 + q1.y;
            acc[i][jn][0] = v0; acc[i][jn][1] = v1;
            acc[i][jn][2] = v2; acc[i][jn][3] = v3;
            *(float2*)(X2 + off0) = make_float2(v0, v1);
            *(float2*)(X2 + off1) = make_float2(v2, v3);
            s0[jn * 2 + 0] += v0 + v2;
            s0[jn * 2 + 1] += v1 + v3;
            s1[jn * 2 + 0] += v0 * v0 + v2 * v2;
            s1[jn * 2 + 1] += v1 * v1 + v3 * v3;
        }
    }

#pragma unroll
    for (int u = 0; u < 8; u++) {
        s0[u] += __shfl_xor_sync(0xffffffffu, s0[u], 4);
        s0[u] += __shfl_xor_sync(0xffffffffu, s0[u], 8);
        s0[u] += __shfl_xor_sync(0xffffffffu, s0[u], 16);
        s1[u] += __shfl_xor_sync(0xffffffffu, s1[u], 4);
        s1[u] += __shfl_xor_sync(0xffffffffu, s1[u], 8);
        s1[u] += __shfl_xor_sync(0xffffffffu, s1[u], 16);
    }
    if (l4 == 0) {
#pragma unroll
        for (int jn = 0; jn < 4; jn++) {
            int c = wn * 32 + jn * 8 + l2;
            pm[wm * 64 + c]     = s0[jn * 2 + 0];
            pm[wm * 64 + c + 1] = s0[jn * 2 + 1];
            pq[wm * 64 + c]     = s1[jn * 2 + 0];
            pq[wm * 64 + c + 1] = s1[jn * 2 + 1];
        }
    }
    __syncthreads();
    if (tid < 64) {
        float sm_ = pm[tid] + pm[64 + tid] + pm[128 + tid] + pm[192 + tid];
        float sq_ = pq[tid] + pq[64 + tid] + pq[128 + tid] + pq[192 + tid];
        float mu  = sm_ * (1.0f / CCH);
        float var = sq_ * (1.0f / CCH) - mu * mu;
        msm[tid] = mu;
        rsm[tid] = rsqrtf(var + 1e-5f);
    }
    __syncthreads();

#pragma unroll
    for (int i = 0; i < 4; i++) {
        int r0 = wm * 64 + i * 16 + l4;
        int r1 = r0 + 8;
        float sc0 = ln_s[r0], sb0 = ln_b[r0];
        float sc1 = ln_s[r1], sb1 = ln_b[r1];
#pragma unroll
        for (int jn = 0; jn < 4; jn++) {
            int c = wn * 32 + jn * 8 + l2;
            int col = p0 + c;
            float mu0 = msm[c], r_0 = rsm[c];
            float mu1 = msm[c + 1], r_1 = rsm[c + 1];
            size_t off0 = (size_t)b * CCH * HW + (size_t)r0 * HW + col;
            size_t off1 = (size_t)b * CCH * HW + (size_t)r1 * HW + col;
            float y0 = (acc[i][jn][0] - mu0) * r_0 * sc0 + sb0;
            float y1 = (acc[i][jn][1] - mu1) * r_1 * sc0 + sb0;
            float y2 = (acc[i][jn][2] - mu0) * r_0 * sc1 + sb1;
            float y3 = (acc[i][jn][3] - mu1) * r_1 * sc1 + sb1;
            *(unsigned int*)(Xln + off0) = pack_bf2(y0, y1);
            *(unsigned int*)(Xln + off1) = pack_bf2(y2, y3);
        }
    }
}

// ---------------- tensor-core chunked attention (unchanged) ----------------
__global__ __launch_bounds__(128)
void attn_mma_kernel(const __nv_bfloat16* __restrict__ qkv, __nv_bfloat16* __restrict__ out)
{
    extern __shared__ __nv_bfloat16 ats[];
    __nv_bfloat16* QVs = ats + AT_QV;
    __nv_bfloat16* Ksm = ats + AT_K;
    __nv_bfloat16* Psm = ats + AT_P;

    unsigned int qv_base = (unsigned int)__cvta_generic_to_shared(QVs);
    unsigned int k_base  = (unsigned int)__cvta_generic_to_shared(Ksm);
    unsigned int p_base  = (unsigned int)__cvta_generic_to_shared(Psm);

    int g = blockIdx.x, b = blockIdx.y;
    int tid = threadIdx.x;
    int warp = tid >> 5, lane = tid & 31;
    const __nv_bfloat16* base = qkv + (size_t)b * 3 * CCH * HW + (size_t)g * CHUNK;

#pragma unroll
    for (int k = 0; k < 16; k++) {
        int e = k * 128 + tid;
        int c = e >> 3, seg = (e & 7) * 8;
        cp_async16(qv_base + (c * ATS + seg) * 2, base + (size_t)c * HW + seg);
        cp_async16(k_base  + (c * ATS + seg) * 2, base + (size_t)(256 + c) * HW + seg);
    }
    cp_commit();
    cp_wait0();
    __syncthreads();

    int i0 = warp * 16;
    float acc[8][4];
#pragma unroll
    for (int t = 0; t < 8; t++)
#pragma unroll
        for (int q = 0; q < 4; q++) acc[t][q] = 0.f;

    int a_c = (lane & 7) + ((lane >> 4) << 3);
    int a_m = i0 + ((lane >> 3) & 1) * 8;
    int b_c = (lane & 15);
    int b_j = (lane >> 4) * 8;

#pragma unroll
    for (int kk = 0; kk < 16; kk++) {
        unsigned int af[4];
        ldsm_x4_t(af, qv_base + (((kk * 16 + a_c) * ATS) + a_m) * 2);
#pragma unroll
        for (int jt = 0; jt < 4; jt++) {
            unsigned int bfr[4];
            ldsm_x4_t(bfr, k_base + (((kk * 16 + b_c) * ATS) + jt * 16 + b_j) * 2);
            mma_bf16(acc[jt * 2 + 0], af, &bfr[0]);
            mma_bf16(acc[jt * 2 + 1], af, &bfr[2]);
        }
    }

    {
        const float SC = 0.0625f;
#pragma unroll
        for (int t = 0; t < 8; t++)
#pragma unroll
            for (int q = 0; q < 4; q++) acc[t][q] *= SC;

        float mxA = -1e30f, mxB = -1e30f;
#pragma unroll
        for (int t = 0; t < 8; t++) {
            mxA = fmaxf(mxA, fmaxf(acc[t][0], acc[t][1]));
            mxB = fmaxf(mxB, fmaxf(acc[t][2], acc[t][3]));
        }
        mxA = fmaxf(mxA, __shfl_xor_sync(0xffffffffu, mxA, 1));
        mxA = fmaxf(mxA, __shfl_xor_sync(0xffffffffu, mxA, 2));
        mxB = fmaxf(mxB, __shfl_xor_sync(0xffffffffu, mxB, 1));
        mxB = fmaxf(mxB, __shfl_xor_sync(0xffffffffu, mxB, 2));

        float sA = 0.f, sB = 0.f;
#pragma unroll
        for (int t = 0; t < 8; t++) {
            acc[t][0] = expf(acc[t][0] - mxA); sA += acc[t][0];
            acc[t][1] = expf(acc[t][1] - mxA); sA += acc[t][1];
            acc[t][2] = expf(acc[t][2] - mxB); sB += acc[t][2];
            acc[t][3] = expf(acc[t][3] - mxB); sB += acc[t][3];
        }
        sA += __shfl_xor_sync(0xffffffffu, sA, 1);
        sA += __shfl_xor_sync(0xffffffffu, sA, 2);
        sB += __shfl_xor_sync(0xffffffffu, sB, 1);
        sB += __shfl_xor_sync(0xffffffffu, sB, 2);
        float iA = 1.0f / sA, iB = 1.0f / sB;
#pragma unroll
        for (int t = 0; t < 8; t++) {
            acc[t][0] *= iA; acc[t][1] *= iA;
            acc[t][2] *= iB; acc[t][3] *= iB;
        }
    }

    __syncthreads();

#pragma unroll
    for (int k = 0; k < 16; k++) {
        int e = k * 128 + tid;
        int c = e >> 3, seg = (e & 7) * 8;
        cp_async16(qv_base + (c * ATS + seg) * 2, base + (size_t)(512 + c) * HW + seg);
    }
    cp_commit();
    {
        int r = i0 + (lane >> 2);
#pragma unroll
        for (int t = 0; t < 8; t++) {
            int jc = t * 8 + (lane & 3) * 2;
            *(unsigned int*)(Psm + r * ATS + jc)       = pack_bf2(acc[t][0], acc[t][1]);
            *(unsigned int*)(Psm + (r + 8) * ATS + jc) = pack_bf2(acc[t][2], acc[t][3]);
        }
    }
    cp_wait0();
    __syncthreads();

    int ap_r = (lane & 15);
    int ap_k = (lane >> 4) * 8;
    int bv_n = (lane & 7) + ((lane >> 4) << 3);
    int bv_k = ((lane >> 3) & 1) * 8;

#pragma unroll
    for (int pass = 0; pass < 2; pass++) {
        int cbase = warp * 64 + pass * 32;
        float oc[4][4][4];
#pragma unroll
        for (int it = 0; it < 4; it++)
#pragma unroll
            for (int nn = 0; nn < 4; nn++)
#pragma unroll
                for (int q = 0; q < 4; q++) oc[it][nn][q] = 0.f;

#pragma unroll
        for (int kk = 0; kk < 4; kk++) {
            unsigned int ap[4][4];
#pragma unroll
            for (int it = 0; it < 4; it++)
                ldsm_x4(ap[it], p_base + (((it * 16 + ap_r) * ATS) + kk * 16 + ap_k) * 2);
            unsigned int bv[2][4];
#pragma unroll
            for (int nt = 0; nt < 2; nt++)
                ldsm_x4(bv[nt], qv_base + (((cbase + nt * 16 + bv_n) * ATS) + kk * 16 + bv_k) * 2);
#pragma unroll
            for (int it = 0; it < 4; it++)
#pragma unroll
                for (int nn = 0; nn < 4; nn++)
                    mma_bf16(oc[it][nn], ap[it], &bv[nn >> 1][(nn & 1) * 2]);
        }

#pragma unroll
        for (int it = 0; it < 4; it++) {
            int r = it * 16 + (lane >> 2);
#pragma unroll
            for (int nn = 0; nn < 4; nn++) {
                int cc = cbase + nn * 8 + (lane & 3) * 2;
                Ksm[cc * ATS + r]           = __float2bfloat16(oc[it][nn][0]);
                Ksm[(cc + 1) * ATS + r]     = __float2bfloat16(oc[it][nn][1]);
                Ksm[cc * ATS + r + 8]       = __float2bfloat16(oc[it][nn][2]);
                Ksm[(cc + 1) * ATS + r + 8] = __float2bfloat16(oc[it][nn][3]);
            }
        }
    }
    __syncthreads();

    __nv_bfloat16* op = out + (size_t)b * CCH * HW + (size_t)g * CHUNK;
#pragma unroll
    for (int k = 0; k < 16; k++) {
        int e = k * 128 + tid;
        int c = e >> 3, seg = (e & 7) * 8;
        *(uint4*)(op + (size_t)c * HW + seg) = *(uint4*)(Ksm + c * ATS + seg);
    }
}

// ---------------- depthwise 3x3 conv + bias + gelu ----------------
__global__ void dwconv_kernel(const __nv_bfloat16* __restrict__ in,
                              const float* __restrict__ w,
                              const float* __restrict__ bias,
                              __nv_bfloat16* __restrict__ out)
{
    int idx = blockIdx.x * 256 + threadIdx.x;
    int x = idx & 127;
    int y = (idx >> 7) & 127;
    int c = (idx >> 14) & (HID - 1);
    const __nv_bfloat16* ip = in + ((size_t)(idx >> 14) << 14);
    const float* wp = w + c * 9;

    float acc = 0.f;
#pragma unroll
    for (int ky = 0; ky < 3; ky++) {
        int yy = y + ky - 1;
        if (yy < 0 || yy > 127) continue;
#pragma unroll
        for (int kx = 0; kx < 3; kx++) {
            int xx = x + kx - 1;
            if (xx < 0 || xx > 127) continue;
            acc += __bfloat162float(ip[yy * 128 + xx]) * wp[ky * 3 + kx];
        }
    }
    acc += bias[c];
    out[idx] = __float2bfloat16(gelu_f(acc));
}

// ---------------- launcher ----------------
extern "C" void kernel_launch(void* const* d_in, const int* in_sizes, int n_in,
                              void* d_out, int out_size)
{
    const float* x       = (const float*)d_in[0];
    const float* ln1_s   = (const float*)d_in[1];
    const float* ln1_b   = (const float*)d_in[2];
    const float* qkv_w   = (const float*)d_in[3];
    const float* qkv_b   = (const float*)d_in[4];
    const float* proj_w  = (const float*)d_in[5];
    const float* proj_b  = (const float*)d_in[6];
    const float* ln2_s   = (const float*)d_in[7];
    const float* ln2_b   = (const float*)d_in[8];
    const float* conv1_w = (const float*)d_in[9];
    const float* conv1_b = (const float*)d_in[10];
    const float* conv2_w = (const float*)d_in[11];
    const float* conv2_b = (const float*)d_in[12];
    const float* conv3_w = (const float*)d_in[13];
    const float* conv3_b = (const float*)d_in[14];
    float* outp = (float*)d_out;

    __nv_bfloat16 *xln, *qkv, *attnp, *h1, *h2, *wbf;
    float *x2;
    cudaGetSymbolAddress((void**)&xln,   g_xln);
    cudaGetSymbolAddress((void**)&qkv,   g_qkv);
    cudaGetSymbolAddress((void**)&attnp, g_attn);
    cudaGetSymbolAddress((void**)&x2,    g_x2);
    cudaGetSymbolAddress((void**)&h1,    g_h1);
    cudaGetSymbolAddress((void**)&h2,    g_h2);
    cudaGetSymbolAddress((void**)&wbf,   g_wbf);

    __nv_bfloat16* w_qkv = wbf;
    __nv_bfloat16* w_prj = w_qkv + 768 * 256;
    __nv_bfloat16* w_c1  = w_prj + 256 * 256;
    __nv_bfloat16* w_c3  = w_c1 + 512 * 256;

    cudaFuncSetAttribute(attn_mma_kernel, cudaFuncAttributeMaxDynamicSharedMemorySize, AT_SMEM_BYTES);
    cudaFuncSetAttribute(ln_kernel, cudaFuncAttributeMaxDynamicSharedMemorySize, LN_SMEM_BYTES);
    cudaFuncSetAttribute(gemm_bf16_kernel, cudaFuncAttributeMaxDynamicSharedMemorySize, GE_SMEM);
    cudaFuncSetAttribute(proj_ln2_kernel, cudaFuncAttributeMaxDynamicSharedMemorySize, PJ_SMEM);

    // 0) weight conversion
    cvt_all_kernel<<<524288 / 256, 256>>>(qkv_w, proj_w, conv1_w, conv3_w, wbf);

    // 1) LN1
    ln_kernel<<<BATCH * 256, 256, LN_SMEM_BYTES>>>(x, ln1_s, ln1_b, xln);

    // 2) QKV GEMM -> qkv bf16
    gemm_bf16_kernel<<<dim3(HW / BN, 768 / BM, BATCH), 128, GE_SMEM>>>(
        w_qkv, xln, qkv_b, nullptr, qkv, 256,
        (long)CCH * HW, (long)3 * CCH * HW, 0);

    // 3) attention -> attn bf16
    attn_mma_kernel<<<dim3(NG, BATCH), 128, AT_SMEM_BYTES>>>(qkv, attnp);

    // 4) proj GEMM + residual + LN2 -> x2 fp32, xln bf16 (fused)
    proj_ln2_kernel<<<dim3(HW / 64, 1, BATCH), 256, PJ_SMEM>>>(
        w_prj, attnp, proj_b, x, ln2_s, ln2_b, x2, xln);

    // 5) conv1 (1x1) + gelu -> h1 bf16
    gemm_bf16_kernel<<<dim3(HW / BN, 512 / BM, BATCH), 128, GE_SMEM>>>(
        w_c1, xln, conv1_b, nullptr, h1, 256,
        (long)CCH * HW, (long)HID * HW, 2);

    // 6) depthwise 3x3 + gelu -> h2 bf16
    dwconv_kernel<<<BATCH * HID * HW / 256, 256>>>(h1, conv2_w, conv2_b, h2);

    // 7) conv3 (1x1) + residual(x2) -> out fp32
    gemm_bf16_kernel<<<dim3(HW / BN, 256 / BM, BATCH), 128, GE_SMEM>>>(
        w_c3, h2, conv3_b, x2, outp, 512,
        (long)HID * HW, (long)CCH * HW, 1);
}

// round 9
// speedup vs baseline: 1.2399x; 1.2399x over previous
#include <cuda_runtime.h>
#include <cuda_bf16.h>
#include <cstdint>
#include <cstddef>
#include <math.h>

// Problem constants
#define BATCH 8
#define CCH   256
#define HW    16384
#define HID   512
#define CHUNK 64
#define NG    (HW / CHUNK)

// Generic GEMM tiling: 128x128, BK=32, 4-stage pipeline (R7 winner config)
#define BM 128
#define BN 128
#define BK 32
#define ASTRIDE 40
#define BSTRIDE 136
#define ASZB (BM * ASTRIDE * 2)     // 10240 B per A stage
#define BSZB (BK * BSTRIDE * 2)     // 8704 B per B stage
#define GSTG 4
#define GE_SMEM (GSTG * (ASZB + BSZB))   // 75776 B

// Fused proj+LN2: M=256, N=64, BK=32, 3-stage
#define PASTR 40
#define PBSTR 72
#define PASZB (256 * PASTR * 2)     // 20480 B
#define PBSZB (32 * PBSTR * 2)      // 4608 B
#define PSTG 3
#define PJ_RED (PSTG * (PASZB + PBSZB))          // 75264
#define PJ_SMEM (PJ_RED + 1024 + 1024 + 256 + 256) // 77824 B

// attention smem layout (bf16 elems), row stride 72
#define ATS 72
#define AT_QV 0
#define AT_K  (256 * ATS)
#define AT_P  (512 * ATS)
#define AT_ELEMS (512 * ATS + 64 * ATS)
#define AT_SMEM_BYTES (AT_ELEMS * 2)

// LN smem
#define LN_SMEM_BYTES (256 * 65 * 4 + 128 * 4)

// ---------------- scratch ----------------
__device__ __nv_bfloat16 g_xln [BATCH * CCH * HW];
__device__ __nv_bfloat16 g_qkv [BATCH * 3 * CCH * HW];
__device__ __nv_bfloat16 g_attn[BATCH * CCH * HW];
__device__ float         g_x2  [BATCH * CCH * HW];
__device__ __nv_bfloat16 g_h1  [BATCH * HID * HW];
__device__ __nv_bfloat16 g_h2  [BATCH * HID * HW];
__device__ __nv_bfloat16 g_wbf [768*256 + 256*256 + 512*256 + 256*512];

__device__ __forceinline__ float gelu_f(float v) {
    return 0.5f * v * (1.0f + erff(v * 0.70710678118654752f));
}

union BF2U { __nv_bfloat162 h; unsigned int u; };
__device__ __forceinline__ unsigned int pack_bf2(float a, float b) {
    BF2U t; t.h = __floats2bfloat162_rn(a, b); return t.u;
}
union BFV8 { uint4 q; __nv_bfloat16 h[8]; };

// ---------------- helpers ----------------
__device__ __forceinline__ void ldsm_x4(unsigned int* r, unsigned int addr) {
    asm volatile("ldmatrix.sync.aligned.m8n8.x4.shared.b16 {%0,%1,%2,%3}, [%4];"
                 : "=r"(r[0]), "=r"(r[1]), "=r"(r[2]), "=r"(r[3]) : "r"(addr));
}
__device__ __forceinline__ void ldsm_x4_t(unsigned int* r, unsigned int addr) {
    asm volatile("ldmatrix.sync.aligned.m8n8.x4.trans.shared.b16 {%0,%1,%2,%3}, [%4];"
                 : "=r"(r[0]), "=r"(r[1]), "=r"(r[2]), "=r"(r[3]) : "r"(addr));
}
__device__ __forceinline__ void mma_bf16(float* d, const unsigned int* a, const unsigned int* b) {
    asm volatile("mma.sync.aligned.m16n8k16.row.col.f32.bf16.bf16.f32 "
                 "{%0,%1,%2,%3}, {%4,%5,%6,%7}, {%8,%9}, {%0,%1,%2,%3};"
                 : "+f"(d[0]), "+f"(d[1]), "+f"(d[2]), "+f"(d[3])
                 : "r"(a[0]), "r"(a[1]), "r"(a[2]), "r"(a[3]), "r"(b[0]), "r"(b[1]));
}
__device__ __forceinline__ void cp_async16(unsigned int dst, const void* src) {
    asm volatile("cp.async.cg.shared.global [%0], [%1], 16;" :: "r"(dst), "l"(src));
}
__device__ __forceinline__ void cp_commit() {
    asm volatile("cp.async.commit_group;" ::: "memory");
}
__device__ __forceinline__ void cp_wait0() {
    asm volatile("cp.async.wait_group 0;" ::: "memory");
}
__device__ __forceinline__ void cp_wait1() {
    asm volatile("cp.async.wait_group 1;" ::: "memory");
}
__device__ __forceinline__ void cp_wait2() {
    asm volatile("cp.async.wait_group 2;" ::: "memory");
}

// ---------------- merged weight fp32 -> bf16 ----------------
__global__ void cvt_all_kernel(const float* __restrict__ s0, const float* __restrict__ s1,
                               const float* __restrict__ s2, const float* __restrict__ s3,
                               __nv_bfloat16* __restrict__ dst)
{
    int i = blockIdx.x * 256 + threadIdx.x;
    const float* s; int off;
    if (i < 196608)      { s = s0; off = i; }
    else if (i < 262144) { s = s1; off = i - 196608; }
    else if (i < 393216) { s = s2; off = i - 262144; }
    else                 { s = s3; off = i - 393216; }
    dst[i] = __float2bfloat16(s[off]);
}

// ---------------- single-pass LayerNorm (LN1) ----------------
__global__ __launch_bounds__(256)
void ln_kernel(const float* __restrict__ in,
               const float* __restrict__ scale,
               const float* __restrict__ bias,
               __nv_bfloat16* __restrict__ out)
{
    extern __shared__ float lns[];
    float* ts  = lns;
    float* mus = lns + 256 * 65;
    float* rs  = mus + 64;

    int bp = blockIdx.x;
    int b  = bp >> 8;
    int p0 = (bp & 255) * 64;
    int tid = threadIdx.x;
    const float* ip = in + (size_t)b * CCH * HW + p0;

#pragma unroll
    for (int k = 0; k < 64; k++) {
        int e = k * 256 + tid;
        int c = e >> 6, p = e & 63;
        ts[c * 65 + p] = ip[(size_t)c * HW + p];
    }
    __syncthreads();

    {
        int tq = tid & 3, pp = tid >> 2;
        float s = 0.f, s2 = 0.f;
#pragma unroll 16
        for (int j = 0; j < 64; j++) {
            float v = ts[(tq + 4 * j) * 65 + pp];
            s += v; s2 += v * v;
        }
        s  += __shfl_xor_sync(0xffffffffu, s, 1);
        s  += __shfl_xor_sync(0xffffffffu, s, 2);
        s2 += __shfl_xor_sync(0xffffffffu, s2, 1);
        s2 += __shfl_xor_sync(0xffffffffu, s2, 2);
        float mu  = s * (1.0f / CCH);
        float var = s2 * (1.0f / CCH) - mu * mu;
        if (tq == 0) { mus[pp] = mu; rs[pp] = rsqrtf(var + 1e-5f); }
    }
    __syncthreads();

    __nv_bfloat16* op = out + (size_t)b * CCH * HW + p0;
#pragma unroll
    for (int k = 0; k < 64; k++) {
        int e = k * 256 + tid;
        int c = e >> 6, p = e & 63;
        float v = ts[c * 65 + p];
        op[(size_t)c * HW + p] = __float2bfloat16((v - mus[p]) * rs[p] * scale[c] + bias[c]);
    }
}

// ---------------- bf16 mma.sync GEMM, 128x128 tile, 4-stage pipeline (R7 winner) ----
// epi: 0 = +bias -> bf16 ; 1 = +bias + Res(fp32) -> fp32 ; 2 = gelu(+bias) -> bf16
__global__ __launch_bounds__(256, 2)
void gemm_bf16_kernel(const __nv_bfloat16* __restrict__ A,
                      const __nv_bfloat16* __restrict__ Bact,
                      const float* __restrict__ bias,
                      const float* __restrict__ Res,
                      void* __restrict__ Cout,
                      int K, long strideB, long strideC, int epi)
{
    extern __shared__ __nv_bfloat16 gsm[];
    unsigned int as_base = (unsigned int)__cvta_generic_to_shared(gsm);
    unsigned int bs_base = as_base + GSTG * ASZB;

    int tid = threadIdx.x;
    int m0 = blockIdx.y * BM;
    int p0 = blockIdx.x * BN;
    int b  = blockIdx.z;
    const __nv_bfloat16* Bp = Bact + (size_t)b * strideB + p0;
    const __nv_bfloat16* Ap = A + (size_t)m0 * K;

    int ar0 = tid >> 2, ac = (tid & 3) * 8;
    int br0 = tid >> 4, bc = (tid & 15) * 8;

    unsigned int sa0 = (ar0 * ASTRIDE + ac) * 2;
    unsigned int sa1 = ((ar0 + 64) * ASTRIDE + ac) * 2;
    unsigned int sb0 = (br0 * BSTRIDE + bc) * 2;
    unsigned int sb1 = ((br0 + 16) * BSTRIDE + bc) * 2;

    int nk = K >> 5;

#pragma unroll
    for (int s = 0; s < GSTG - 1; s++) {
        if (s < nk) {
            int k0 = s * BK;
            unsigned int ao = as_base + s * ASZB;
            unsigned int bo = bs_base + s * BSZB;
            cp_async16(ao + sa0, Ap + (size_t)ar0 * K + k0 + ac);
            cp_async16(ao + sa1, Ap + (size_t)(ar0 + 64) * K + k0 + ac);
            cp_async16(bo + sb0, Bp + (size_t)(k0 + br0) * HW + bc);
            cp_async16(bo + sb1, Bp + (size_t)(k0 + br0 + 16) * HW + bc);
        }
        cp_commit();
    }

    int warp = tid >> 5, lane = tid & 31;
    int wm = warp >> 2;
    int wn = warp & 3;

    float acc[4][4][4];
#pragma unroll
    for (int i = 0; i < 4; i++)
#pragma unroll
        for (int j = 0; j < 4; j++)
#pragma unroll
            for (int q = 0; q < 4; q++) acc[i][j][q] = 0.f;

    int a_row = wm * 64 + (lane & 15);
    int a_col = (lane >> 4) * 8;
    int b_row = (lane & 15);
    int b_col = wn * 32 + (lane >> 4) * 8;

    for (int kt = 0; kt < nk; kt++) {
        cp_wait2();
        __syncthreads();

        int ps = kt + GSTG - 1;
        if (ps < nk) {
            int k0 = ps * BK;
            unsigned int ao = as_base + (ps & (GSTG - 1)) * ASZB;
            unsigned int bo = bs_base + (ps & (GSTG - 1)) * BSZB;
            cp_async16(ao + sa0, Ap + (size_t)ar0 * K + k0 + ac);
            cp_async16(ao + sa1, Ap + (size_t)(ar0 + 64) * K + k0 + ac);
            cp_async16(bo + sb0, Bp + (size_t)(k0 + br0) * HW + bc);
            cp_async16(bo + sb1, Bp + (size_t)(k0 + br0 + 16) * HW + bc);
        }
        cp_commit();

        unsigned int abase = as_base + (kt & (GSTG - 1)) * ASZB;
        unsigned int bbase = bs_base + (kt & (GSTG - 1)) * BSZB;
#pragma unroll
        for (int kk = 0; kk < 2; kk++) {
            unsigned int af[4][4];
            unsigned int bfr[2][4];
#pragma unroll
            for (int i = 0; i < 4; i++)
                ldsm_x4(af[i], abase + (((a_row + i * 16) * ASTRIDE) + a_col + kk * 16) * 2);
#pragma unroll
            for (int j = 0; j < 2; j++)
                ldsm_x4_t(bfr[j], bbase + (((b_row + kk * 16) * BSTRIDE) + b_col + j * 16) * 2);
#pragma unroll
            for (int i = 0; i < 4; i++)
#pragma unroll
                for (int jn = 0; jn < 4; jn++)
                    mma_bf16(acc[i][jn], af[i], &bfr[jn >> 1][(jn & 1) * 2]);
        }
    }

    int l4 = lane >> 2, l2 = (lane & 3) * 2;
#pragma unroll
    for (int i = 0; i < 4; i++) {
        int r0 = m0 + wm * 64 + i * 16 + l4;
        int r1 = r0 + 8;
        float bv0 = bias[r0], bv1 = bias[r1];
#pragma unroll
        for (int jn = 0; jn < 4; jn++) {
            int col = p0 + wn * 32 + jn * 8 + l2;
            size_t off0 = (size_t)b * strideC + (size_t)r0 * HW + col;
            size_t off1 = (size_t)b * strideC + (size_t)r1 * HW + col;
            float v0 = acc[i][jn][0] + bv0;
            float v1 = acc[i][jn][1] + bv0;
            float v2 = acc[i][jn][2] + bv1;
            float v3 = acc[i][jn][3] + bv1;
            if (epi == 1) {
                float* Cf = (float*)Cout;
                float2 q0 = *(const float2*)(Res + off0);
                float2 q1 = *(const float2*)(Res + off1);
                *(float2*)(Cf + off0) = make_float2(v0 + q0.x, v1 + q0.y);
                *(float2*)(Cf + off1) = make_float2(v2 + q1.x, v3 + q1.y);
            } else {
                if (epi == 2) {
                    v0 = gelu_f(v0); v1 = gelu_f(v1);
                    v2 = gelu_f(v2); v3 = gelu_f(v3);
                }
                __nv_bfloat16* Cb = (__nv_bfloat16*)Cout;
                *(unsigned int*)(Cb + off0) = pack_bf2(v0, v1);
                *(unsigned int*)(Cb + off1) = pack_bf2(v2, v3);
            }
        }
    }
}

// ---------------- fused proj GEMM + residual + LN2 (unchanged from R7) ----------------
__global__ __launch_bounds__(256, 2)
void proj_ln2_kernel(const __nv_bfloat16* __restrict__ Wp,
                     const __nv_bfloat16* __restrict__ Bact,
                     const float* __restrict__ bias,
                     const float* __restrict__ Resx,
                     const float* __restrict__ ln_s,
                     const float* __restrict__ ln_b,
                     float* __restrict__ X2,
                     __nv_bfloat16* __restrict__ Xln)
{
    extern __shared__ __nv_bfloat16 psm[];
    unsigned int as_base = (unsigned int)__cvta_generic_to_shared(psm);
    unsigned int bs_base = as_base + PSTG * PASZB;
    float* pm  = (float*)((char*)psm + PJ_RED);
    float* pq  = pm + 4 * 64;
    float* msm = pq + 4 * 64;
    float* rsm = msm + 64;

    int tid = threadIdx.x;
    int p0 = blockIdx.x * 64;
    int b  = blockIdx.z;
    const __nv_bfloat16* Bp = Bact + (size_t)b * CCH * HW + p0;

    int ar = tid >> 2, ac = (tid & 3) * 8;
    int br = tid >> 3, bc = (tid & 7) * 8;

#pragma unroll
    for (int s = 0; s < PSTG - 1; s++) {
        int k0 = s * 32;
        unsigned int ao = as_base + s * PASZB;
        unsigned int bo = bs_base + s * PBSZB;
#pragma unroll
        for (int i = 0; i < 4; i++) {
            int r = ar + i * 64;
            cp_async16(ao + (r * PASTR + ac) * 2, Wp + (size_t)r * 256 + k0 + ac);
        }
        cp_async16(bo + (br * PBSTR + bc) * 2, Bp + (size_t)(k0 + br) * HW + bc);
        cp_commit();
    }

    int warp = tid >> 5, lane = tid & 31;
    int wm = warp >> 1;
    int wn = warp & 1;

    float acc[4][4][4];
#pragma unroll
    for (int i = 0; i < 4; i++)
#pragma unroll
        for (int j = 0; j < 4; j++)
#pragma unroll
            for (int q = 0; q < 4; q++) acc[i][j][q] = 0.f;

    int a_row = wm * 64 + (lane & 15);
    int a_col = (lane >> 4) * 8;
    int b_row = (lane & 15);
    int b_col = wn * 32 + (lane >> 4) * 8;

    for (int kt = 0; kt < 8; kt++) {
        cp_wait1();
        __syncthreads();

        int ps = kt + PSTG - 1;
        if (ps < 8) {
            int k0 = ps * 32;
            unsigned int ao = as_base + (ps % PSTG) * PASZB;
            unsigned int bo = bs_base + (ps % PSTG) * PBSZB;
#pragma unroll
            for (int i = 0; i < 4; i++) {
                int r = ar + i * 64;
                cp_async16(ao + (r * PASTR + ac) * 2, Wp + (size_t)r * 256 + k0 + ac);
            }
            cp_async16(bo + (br * PBSTR + bc) * 2, Bp + (size_t)(k0 + br) * HW + bc);
        }
        cp_commit();

        unsigned int abase = as_base + (kt % PSTG) * PASZB;
        unsigned int bbase = bs_base + (kt % PSTG) * PBSZB;
#pragma unroll
        for (int kk = 0; kk < 2; kk++) {
            unsigned int af[4][4];
            unsigned int bfr[2][4];
#pragma unroll
            for (int i = 0; i < 4; i++)
                ldsm_x4(af[i], abase + (((a_row + i * 16) * PASTR) + a_col + kk * 16) * 2);
#pragma unroll
            for (int j = 0; j < 2; j++)
                ldsm_x4_t(bfr[j], bbase + (((b_row + kk * 16) * PBSTR) + b_col + j * 16) * 2);
#pragma unroll
            for (int i = 0; i < 4; i++)
#pragma unroll
                for (int jn = 0; jn < 4; jn++)
                    mma_bf16(acc[i][jn], af[i], &bfr[jn >> 1][(jn & 1) * 2]);
        }
    }

    int l4 = lane >> 2, l2 = (lane & 3) * 2;
    float s0[8], s1[8];
#pragma unroll
    for (int u = 0; u < 8; u++) { s0[u] = 0.f; s1[u] = 0.f; }

#pragma unroll
    for (int i = 0; i < 4; i++) {
        int r0 = wm * 64 + i * 16 + l4;
        int r1 = r0 + 8;
        float bv0 = bias[r0], bv1 = bias[r1];
#pragma unroll
        for (int jn = 0; jn < 4; jn++) {
            int col = p0 + wn * 32 + jn * 8 + l2;
            size_t off0 = (size_t)b * CCH * HW + (size_t)r0 * HW + col;
            size_t off1 = (size_t)b * CCH * HW + (size_t)r1 * HW + col;
            float2 q0 = *(const float2*)(Resx + off0);
            float2 q1 = *(const float2*)(Resx + off1);
            float v0 = acc[i][jn][0] + bv0 + q0.x;
            float v1 = acc[i][jn][1] + bv0 + q0.y;
            float v2 = acc[i][jn][2] + bv1 + q1.x;
            float v3 = acc[i][jn][3] + bv1 + q1.y;
            acc[i][jn][0] = v0; acc[i][jn][1] = v1;
            acc[i][jn][2] = v2; acc[i][jn][3] = v3;
            *(float2*)(X2 + off0) = make_float2(v0, v1);
            *(float2*)(X2 + off1) = make_float2(v2, v3);
            s0[jn * 2 + 0] += v0 + v2;
            s0[jn * 2 + 1] += v1 + v3;
            s1[jn * 2 + 0] += v0 * v0 + v2 * v2;
            s1[jn * 2 + 1] += v1 * v1 + v3 * v3;
        }
    }

#pragma unroll
    for (int u = 0; u < 8; u++) {
        s0[u] += __shfl_xor_sync(0xffffffffu, s0[u], 4);
        s0[u] += __shfl_xor_sync(0xffffffffu, s0[u], 8);
        s0[u] += __shfl_xor_sync(0xffffffffu, s0[u], 16);
        s1[u] += __shfl_xor_sync(0xffffffffu, s1[u], 4);
        s1[u] += __shfl_xor_sync(0xffffffffu, s1[u], 8);
        s1[u] += __shfl_xor_sync(0xffffffffu, s1[u], 16);
    }
    if (l4 == 0) {
#pragma unroll
        for (int jn = 0; jn < 4; jn++) {
            int c = wn * 32 + jn * 8 + l2;
            pm[wm * 64 + c]     = s0[jn * 2 + 0];
            pm[wm * 64 + c + 1] = s0[jn * 2 + 1];
            pq[wm * 64 + c]     = s1[jn * 2 + 0];
            pq[wm * 64 + c + 1] = s1[jn * 2 + 1];
        }
    }
    __syncthreads();
    if (tid < 64) {
        float sm_ = pm[tid] + pm[64 + tid] + pm[128 + tid] + pm[192 + tid];
        float sq_ = pq[tid] + pq[64 + tid] + pq[128 + tid] + pq[192 + tid];
        float mu  = sm_ * (1.0f / CCH);
        float var = sq_ * (1.0f / CCH) - mu * mu;
        msm[tid] = mu;
        rsm[tid] = rsqrtf(var + 1e-5f);
    }
    __syncthreads();

#pragma unroll
    for (int i = 0; i < 4; i++) {
        int r0 = wm * 64 + i * 16 + l4;
        int r1 = r0 + 8;
        float sc0 = ln_s[r0], sb0 = ln_b[r0];
        float sc1 = ln_s[r1], sb1 = ln_b[r1];
#pragma unroll
        for (int jn = 0; jn < 4; jn++) {
            int c = wn * 32 + jn * 8 + l2;
            int col = p0 + c;
            float mu0 = msm[c], r_0 = rsm[c];
            float mu1 = msm[c + 1], r_1 = rsm[c + 1];
            size_t off0 = (size_t)b * CCH * HW + (size_t)r0 * HW + col;
            size_t off1 = (size_t)b * CCH * HW + (size_t)r1 * HW + col;
            float y0 = (acc[i][jn][0] - mu0) * r_0 * sc0 + sb0;
            float y1 = (acc[i][jn][1] - mu1) * r_1 * sc0 + sb0;
            float y2 = (acc[i][jn][2] - mu0) * r_0 * sc1 + sb1;
            float y3 = (acc[i][jn][3] - mu1) * r_1 * sc1 + sb1;
            *(unsigned int*)(Xln + off0) = pack_bf2(y0, y1);
            *(unsigned int*)(Xln + off1) = pack_bf2(y2, y3);
        }
    }
}

// ---------------- tensor-core chunked attention (unchanged) ----------------
__global__ __launch_bounds__(128)
void attn_mma_kernel(const __nv_bfloat16* __restrict__ qkv, __nv_bfloat16* __restrict__ out)
{
    extern __shared__ __nv_bfloat16 ats[];
    __nv_bfloat16* QVs = ats + AT_QV;
    __nv_bfloat16* Ksm = ats + AT_K;
    __nv_bfloat16* Psm = ats + AT_P;

    unsigned int qv_base = (unsigned int)__cvta_generic_to_shared(QVs);
    unsigned int k_base  = (unsigned int)__cvta_generic_to_shared(Ksm);
    unsigned int p_base  = (unsigned int)__cvta_generic_to_shared(Psm);

    int g = blockIdx.x, b = blockIdx.y;
    int tid = threadIdx.x;
    int warp = tid >> 5, lane = tid & 31;
    const __nv_bfloat16* base = qkv + (size_t)b * 3 * CCH * HW + (size_t)g * CHUNK;

#pragma unroll
    for (int k = 0; k < 16; k++) {
        int e = k * 128 + tid;
        int c = e >> 3, seg = (e & 7) * 8;
        cp_async16(qv_base + (c * ATS + seg) * 2, base + (size_t)c * HW + seg);
        cp_async16(k_base  + (c * ATS + seg) * 2, base + (size_t)(256 + c) * HW + seg);
    }
    cp_commit();
    cp_wait0();
    __syncthreads();

    int i0 = warp * 16;
    float acc[8][4];
#pragma unroll
    for (int t = 0; t < 8; t++)
#pragma unroll
        for (int q = 0; q < 4; q++) acc[t][q] = 0.f;

    int a_c = (lane & 7) + ((lane >> 4) << 3);
    int a_m = i0 + ((lane >> 3) & 1) * 8;
    int b_c = (lane & 15);
    int b_j = (lane >> 4) * 8;

#pragma unroll
    for (int kk = 0; kk < 16; kk++) {
        unsigned int af[4];
        ldsm_x4_t(af, qv_base + (((kk * 16 + a_c) * ATS) + a_m) * 2);
#pragma unroll
        for (int jt = 0; jt < 4; jt++) {
            unsigned int bfr[4];
            ldsm_x4_t(bfr, k_base + (((kk * 16 + b_c) * ATS) + jt * 16 + b_j) * 2);
            mma_bf16(acc[jt * 2 + 0], af, &bfr[0]);
            mma_bf16(acc[jt * 2 + 1], af, &bfr[2]);
        }
    }

    {
        const float SC = 0.0625f;
#pragma unroll
        for (int t = 0; t < 8; t++)
#pragma unroll
            for (int q = 0; q < 4; q++) acc[t][q] *= SC;

        float mxA = -1e30f, mxB = -1e30f;
#pragma unroll
        for (int t = 0; t < 8; t++) {
            mxA = fmaxf(mxA, fmaxf(acc[t][0], acc[t][1]));
            mxB = fmaxf(mxB, fmaxf(acc[t][2], acc[t][3]));
        }
        mxA = fmaxf(mxA, __shfl_xor_sync(0xffffffffu, mxA, 1));
        mxA = fmaxf(mxA, __shfl_xor_sync(0xffffffffu, mxA, 2));
        mxB = fmaxf(mxB, __shfl_xor_sync(0xffffffffu, mxB, 1));
        mxB = fmaxf(mxB, __shfl_xor_sync(0xffffffffu, mxB, 2));

        float sA = 0.f, sB = 0.f;
#pragma unroll
        for (int t = 0; t < 8; t++) {
            acc[t][0] = expf(acc[t][0] - mxA); sA += acc[t][0];
            acc[t][1] = expf(acc[t][1] - mxA); sA += acc[t][1];
            acc[t][2] = expf(acc[t][2] - mxB); sB += acc[t][2];
            acc[t][3] = expf(acc[t][3] - mxB); sB += acc[t][3];
        }
        sA += __shfl_xor_sync(0xffffffffu, sA, 1);
        sA += __shfl_xor_sync(0xffffffffu, sA, 2);
        sB += __shfl_xor_sync(0xffffffffu, sB, 1);
        sB += __shfl_xor_sync(0xffffffffu, sB, 2);
        float iA = 1.0f / sA, iB = 1.0f / sB;
#pragma unroll
        for (int t = 0; t < 8; t++) {
            acc[t][0] *= iA; acc[t][1] *= iA;
            acc[t][2] *= iB; acc[t][3] *= iB;
        }
    }

    __syncthreads();

#pragma unroll
    for (int k = 0; k < 16; k++) {
        int e = k * 128 + tid;
        int c = e >> 3, seg = (e & 7) * 8;
        cp_async16(qv_base + (c * ATS + seg) * 2, base + (size_t)(512 + c) * HW + seg);
    }
    cp_commit();
    {
        int r = i0 + (lane >> 2);
#pragma unroll
        for (int t = 0; t < 8; t++) {
            int jc = t * 8 + (lane & 3) * 2;
            *(unsigned int*)(Psm + r * ATS + jc)       = pack_bf2(acc[t][0], acc[t][1]);
            *(unsigned int*)(Psm + (r + 8) * ATS + jc) = pack_bf2(acc[t][2], acc[t][3]);
        }
    }
    cp_wait0();
    __syncthreads();

    int ap_r = (lane & 15);
    int ap_k = (lane >> 4) * 8;
    int bv_n = (lane & 7) + ((lane >> 4) << 3);
    int bv_k = ((lane >> 3) & 1) * 8;

#pragma unroll
    for (int pass = 0; pass < 2; pass++) {
        int cbase = warp * 64 + pass * 32;
        float oc[4][4][4];
#pragma unroll
        for (int it = 0; it < 4; it++)
#pragma unroll
            for (int nn = 0; nn < 4; nn++)
#pragma unroll
                for (int q = 0; q < 4; q++) oc[it][nn][q] = 0.f;

#pragma unroll
        for (int kk = 0; kk < 4; kk++) {
            unsigned int ap[4][4];
#pragma unroll
            for (int it = 0; it < 4; it++)
                ldsm_x4(ap[it], p_base + (((it * 16 + ap_r) * ATS) + kk * 16 + ap_k) * 2);
            unsigned int bv[2][4];
#pragma unroll
            for (int nt = 0; nt < 2; nt++)
                ldsm_x4(bv[nt], qv_base + (((cbase + nt * 16 + bv_n) * ATS) + kk * 16 + bv_k) * 2);
#pragma unroll
            for (int it = 0; it < 4; it++)
#pragma unroll
                for (int nn = 0; nn < 4; nn++)
                    mma_bf16(oc[it][nn], ap[it], &bv[nn >> 1][(nn & 1) * 2]);
        }

#pragma unroll
        for (int it = 0; it < 4; it++) {
            int r = it * 16 + (lane >> 2);
#pragma unroll
            for (int nn = 0; nn < 4; nn++) {
                int cc = cbase + nn * 8 + (lane & 3) * 2;
                Ksm[cc * ATS + r]           = __float2bfloat16(oc[it][nn][0]);
                Ksm[(cc + 1) * ATS + r]     = __float2bfloat16(oc[it][nn][1]);
                Ksm[cc * ATS + r + 8]       = __float2bfloat16(oc[it][nn][2]);
                Ksm[(cc + 1) * ATS + r + 8] = __float2bfloat16(oc[it][nn][3]);
            }
        }
    }
    __syncthreads();

    __nv_bfloat16* op = out + (size_t)b * CCH * HW + (size_t)g * CHUNK;
#pragma unroll
    for (int k = 0; k < 16; k++) {
        int e = k * 128 + tid;
        int c = e >> 3, seg = (e & 7) * 8;
        *(uint4*)(op + (size_t)c * HW + seg) = *(uint4*)(Ksm + c * ATS + seg);
    }
}

// ---------------- vectorized depthwise 3x3 conv + bias + gelu ----------------
// Each thread computes 8 contiguous x-pixels of one (b,c,y) row.
__global__ __launch_bounds__(256)
void dwconv_kernel(const __nv_bfloat16* __restrict__ in,
                   const float* __restrict__ w,
                   const float* __restrict__ bias,
                   __nv_bfloat16* __restrict__ out)
{
    int t = blockIdx.x * 256 + threadIdx.x;   // BATCH*HID*HW/8 threads
    int px0 = t * 8;
    int x0 = px0 & 127;
    int y  = (px0 >> 7) & 127;
    int bc = px0 >> 14;
    int c  = bc & (HID - 1);
    const __nv_bfloat16* ip = in + ((size_t)bc << 14);
    const float* wp = w + c * 9;

    float v[3][10];
#pragma unroll
    for (int r = 0; r < 3; r++) {
        int yy = y + r - 1;
        if (yy < 0 || yy > 127) {
#pragma unroll
            for (int j = 0; j < 10; j++) v[r][j] = 0.f;
        } else {
            const __nv_bfloat16* rp = ip + yy * 128 + x0;
            BFV8 mid; mid.q = *(const uint4*)rp;
#pragma unroll
            for (int j = 0; j < 8; j++) v[r][j + 1] = __bfloat162float(mid.h[j]);
            v[r][0] = (x0 > 0)   ? __bfloat162float(rp[-1]) : 0.f;
            v[r][9] = (x0 < 120) ? __bfloat162float(rp[8])  : 0.f;
        }
    }

    float w0 = wp[0], w1 = wp[1], w2 = wp[2];
    float w3 = wp[3], w4 = wp[4], w5 = wp[5];
    float w6 = wp[6], w7 = wp[7], w8 = wp[8];
    float bv = bias[c];

    unsigned int res[4];
#pragma unroll
    for (int x = 0; x < 8; x += 2) {
        float o0 = bv, o1 = bv;
        o0 += w0 * v[0][x] + w1 * v[0][x + 1] + w2 * v[0][x + 2];
        o0 += w3 * v[1][x] + w4 * v[1][x + 1] + w5 * v[1][x + 2];
        o0 += w6 * v[2][x] + w7 * v[2][x + 1] + w8 * v[2][x + 2];
        o1 += w0 * v[0][x + 1] + w1 * v[0][x + 2] + w2 * v[0][x + 3];
        o1 += w3 * v[1][x + 1] + w4 * v[1][x + 2] + w5 * v[1][x + 3];
        o1 += w6 * v[2][x + 1] + w7 * v[2][x + 2] + w8 * v[2][x + 3];
        res[x >> 1] = pack_bf2(gelu_f(o0), gelu_f(o1));
    }
    *(uint4*)(out + px0) = *(uint4*)res;
}

// ---------------- launcher ----------------
extern "C" void kernel_launch(void* const* d_in, const int* in_sizes, int n_in,
                              void* d_out, int out_size)
{
    const float* x       = (const float*)d_in[0];
    const float* ln1_s   = (const float*)d_in[1];
    const float* ln1_b   = (const float*)d_in[2];
    const float* qkv_w   = (const float*)d_in[3];
    const float* qkv_b   = (const float*)d_in[4];
    const float* proj_w  = (const float*)d_in[5];
    const float* proj_b  = (const float*)d_in[6];
    const float* ln2_s   = (const float*)d_in[7];
    const float* ln2_b   = (const float*)d_in[8];
    const float* conv1_w = (const float*)d_in[9];
    const float* conv1_b = (const float*)d_in[10];
    const float* conv2_w = (const float*)d_in[11];
    const float* conv2_b = (const float*)d_in[12];
    const float* conv3_w = (const float*)d_in[13];
    const float* conv3_b = (const float*)d_in[14];
    float* outp = (float*)d_out;

    __nv_bfloat16 *xln, *qkv, *attnp, *h1, *h2, *wbf;
    float *x2;
    cudaGetSymbolAddress((void**)&xln,   g_xln);
    cudaGetSymbolAddress((void**)&qkv,   g_qkv);
    cudaGetSymbolAddress((void**)&attnp, g_attn);
    cudaGetSymbolAddress((void**)&x2,    g_x2);
    cudaGetSymbolAddress((void**)&h1,    g_h1);
    cudaGetSymbolAddress((void**)&h2,    g_h2);
    cudaGetSymbolAddress((void**)&wbf,   g_wbf);

    __nv_bfloat16* w_qkv = wbf;
    __nv_bfloat16* w_prj = w_qkv + 768 * 256;
    __nv_bfloat16* w_c1  = w_prj + 256 * 256;
    __nv_bfloat16* w_c3  = w_c1 + 512 * 256;

    cudaFuncSetAttribute(attn_mma_kernel, cudaFuncAttributeMaxDynamicSharedMemorySize, AT_SMEM_BYTES);
    cudaFuncSetAttribute(ln_kernel, cudaFuncAttributeMaxDynamicSharedMemorySize, LN_SMEM_BYTES);
    cudaFuncSetAttribute(gemm_bf16_kernel, cudaFuncAttributeMaxDynamicSharedMemorySize, GE_SMEM);
    cudaFuncSetAttribute(proj_ln2_kernel, cudaFuncAttributeMaxDynamicSharedMemorySize, PJ_SMEM);

    // 0) weight conversion
    cvt_all_kernel<<<524288 / 256, 256>>>(qkv_w, proj_w, conv1_w, conv3_w, wbf);

    // 1) LN1
    ln_kernel<<<BATCH * 256, 256, LN_SMEM_BYTES>>>(x, ln1_s, ln1_b, xln);

    // 2) QKV GEMM -> qkv bf16
    gemm_bf16_kernel<<<dim3(HW / BN, 768 / BM, BATCH), 256, GE_SMEM>>>(
        w_qkv, xln, qkv_b, nullptr, qkv, 256,
        (long)CCH * HW, (long)3 * CCH * HW, 0);

    // 3) attention -> attn bf16
    attn_mma_kernel<<<dim3(NG, BATCH), 128, AT_SMEM_BYTES>>>(qkv, attnp);

    // 4) proj GEMM + residual + LN2 -> x2 fp32, xln bf16 (fused)
    proj_ln2_kernel<<<dim3(HW / 64, 1, BATCH), 256, PJ_SMEM>>>(
        w_prj, attnp, proj_b, x, ln2_s, ln2_b, x2, xln);

    // 5) conv1 (1x1) + gelu -> h1 bf16
    gemm_bf16_kernel<<<dim3(HW / BN, 512 / BM, BATCH), 256, GE_SMEM>>>(
        w_c1, xln, conv1_b, nullptr, h1, 256,
        (long)CCH * HW, (long)HID * HW, 2);

    // 6) depthwise 3x3 + gelu -> h2 bf16 (vectorized, 8 px/thread)
    dwconv_kernel<<<BATCH * HID * HW / (256 * 8), 256>>>(h1, conv2_w, conv2_b, h2);

    // 7) conv3 (1x1) + residual(x2) -> out fp32
    gemm_bf16_kernel<<<dim3(HW / BN, 256 / BM, BATCH), 256, GE_SMEM>>>(
        w_c3, h2, conv3_b, x2, outp, 512,
        (long)HID * HW, (long)CCH * HW, 1);
}

// round 10
// speedup vs baseline: 1.2604x; 1.0165x over previous
#include <cuda_runtime.h>
#include <cuda_bf16.h>
#include <cstdint>
#include <cstddef>
#include <math.h>

// Problem constants
#define BATCH 8
#define CCH   256
#define HW    16384
#define HID   512
#define CHUNK 64
#define NG    (HW / CHUNK)

// Generic GEMM tiling: 128x128 CTA, 8 warps x (64x32), BK=64, 3-stage pipeline
#define BM 128
#define BN 128
#define BK 64
#define ASTRIDE 72                   // 64 bf16 + 8 pad
#define BSTRIDE 136                  // 128 bf16 + 8 pad
#define ASZB (BM * ASTRIDE * 2)      // 18432 B per A stage
#define BSZB (BK * BSTRIDE * 2)      // 17408 B per B stage
#define GSTG 3
#define GE_SMEM (GSTG * (ASZB + BSZB))   // 107520 B

// Fused proj+LN2: M=256, N=64, BK=32, 3-stage (unchanged R7 winner)
#define PASTR 40
#define PBSTR 72
#define PASZB (256 * PASTR * 2)
#define PBSZB (32 * PBSTR * 2)
#define PSTG 3
#define PJ_RED (PSTG * (PASZB + PBSZB))
#define PJ_SMEM (PJ_RED + 1024 + 1024 + 256 + 256)

// attention smem layout (bf16 elems), row stride 72
#define ATS 72
#define AT_QV 0
#define AT_K  (256 * ATS)
#define AT_P  (512 * ATS)
#define AT_ELEMS (512 * ATS + 64 * ATS)
#define AT_SMEM_BYTES (AT_ELEMS * 2)

// LN smem
#define LN_SMEM_BYTES (256 * 65 * 4 + 128 * 4)

// ---------------- scratch ----------------
__device__ __nv_bfloat16 g_xln [BATCH * CCH * HW];
__device__ __nv_bfloat16 g_qkv [BATCH * 3 * CCH * HW];
__device__ __nv_bfloat16 g_attn[BATCH * CCH * HW];
__device__ float         g_x2  [BATCH * CCH * HW];
__device__ __nv_bfloat16 g_h1  [BATCH * HID * HW];
__device__ __nv_bfloat16 g_h2  [BATCH * HID * HW];
__device__ __nv_bfloat16 g_wbf [768*256 + 256*256 + 512*256 + 256*512];

__device__ __forceinline__ float gelu_f(float v) {
    return 0.5f * v * (1.0f + erff(v * 0.70710678118654752f));
}

union BF2U { __nv_bfloat162 h; unsigned int u; };
__device__ __forceinline__ unsigned int pack_bf2(float a, float b) {
    BF2U t; t.h = __floats2bfloat162_rn(a, b); return t.u;
}
union BFV8 { uint4 q; __nv_bfloat16 h[8]; };

// ---------------- helpers ----------------
__device__ __forceinline__ void ldsm_x4(unsigned int* r, unsigned int addr) {
    asm volatile("ldmatrix.sync.aligned.m8n8.x4.shared.b16 {%0,%1,%2,%3}, [%4];"
                 : "=r"(r[0]), "=r"(r[1]), "=r"(r[2]), "=r"(r[3]) : "r"(addr));
}
__device__ __forceinline__ void ldsm_x4_t(unsigned int* r, unsigned int addr) {
    asm volatile("ldmatrix.sync.aligned.m8n8.x4.trans.shared.b16 {%0,%1,%2,%3}, [%4];"
                 : "=r"(r[0]), "=r"(r[1]), "=r"(r[2]), "=r"(r[3]) : "r"(addr));
}
__device__ __forceinline__ void mma_bf16(float* d, const unsigned int* a, const unsigned int* b) {
    asm volatile("mma.sync.aligned.m16n8k16.row.col.f32.bf16.bf16.f32 "
                 "{%0,%1,%2,%3}, {%4,%5,%6,%7}, {%8,%9}, {%0,%1,%2,%3};"
                 : "+f"(d[0]), "+f"(d[1]), "+f"(d[2]), "+f"(d[3])
                 : "r"(a[0]), "r"(a[1]), "r"(a[2]), "r"(a[3]), "r"(b[0]), "r"(b[1]));
}
__device__ __forceinline__ void cp_async16(unsigned int dst, const void* src) {
    asm volatile("cp.async.cg.shared.global [%0], [%1], 16;" :: "r"(dst), "l"(src));
}
__device__ __forceinline__ void cp_commit() {
    asm volatile("cp.async.commit_group;" ::: "memory");
}
__device__ __forceinline__ void cp_wait0() {
    asm volatile("cp.async.wait_group 0;" ::: "memory");
}
__device__ __forceinline__ void cp_wait1() {
    asm volatile("cp.async.wait_group 1;" ::: "memory");
}

// ---------------- merged LN1 + weight conversion ----------------
// blocks [0, 2048): LN1 over (b, 64-pos tile) ; blocks [2048, 4096): weight cvt
__global__ __launch_bounds__(256)
void pre_kernel(const float* __restrict__ in,
                const float* __restrict__ scale,
                const float* __restrict__ bias,
                __nv_bfloat16* __restrict__ out,
                const float* __restrict__ s0, const float* __restrict__ s1,
                const float* __restrict__ s2, const float* __restrict__ s3,
                __nv_bfloat16* __restrict__ wdst)
{
    int tid = threadIdx.x;
    if (blockIdx.x >= 2048) {
        int i = (blockIdx.x - 2048) * 256 + tid;
        const float* s; int off;
        if (i < 196608)      { s = s0; off = i; }
        else if (i < 262144) { s = s1; off = i - 196608; }
        else if (i < 393216) { s = s2; off = i - 262144; }
        else                 { s = s3; off = i - 393216; }
        wdst[i] = __float2bfloat16(s[off]);
        return;
    }

    extern __shared__ float lns[];
    float* ts  = lns;
    float* mus = lns + 256 * 65;
    float* rs  = mus + 64;

    int bp = blockIdx.x;
    int b  = bp >> 8;
    int p0 = (bp & 255) * 64;
    const float* ip = in + (size_t)b * CCH * HW + p0;

#pragma unroll
    for (int k = 0; k < 64; k++) {
        int e = k * 256 + tid;
        int c = e >> 6, p = e & 63;
        ts[c * 65 + p] = ip[(size_t)c * HW + p];
    }
    __syncthreads();

    {
        int tq = tid & 3, pp = tid >> 2;
        float s = 0.f, s2 = 0.f;
#pragma unroll 16
        for (int j = 0; j < 64; j++) {
            float v = ts[(tq + 4 * j) * 65 + pp];
            s += v; s2 += v * v;
        }
        s  += __shfl_xor_sync(0xffffffffu, s, 1);
        s  += __shfl_xor_sync(0xffffffffu, s, 2);
        s2 += __shfl_xor_sync(0xffffffffu, s2, 1);
        s2 += __shfl_xor_sync(0xffffffffu, s2, 2);
        float mu  = s * (1.0f / CCH);
        float var = s2 * (1.0f / CCH) - mu * mu;
        if (tq == 0) { mus[pp] = mu; rs[pp] = rsqrtf(var + 1e-5f); }
    }
    __syncthreads();

    __nv_bfloat16* op = out + (size_t)b * CCH * HW + p0;
#pragma unroll
    for (int k = 0; k < 64; k++) {
        int e = k * 256 + tid;
        int c = e >> 6, p = e & 63;
        float v = ts[c * 65 + p];
        op[(size_t)c * HW + p] = __float2bfloat16((v - mus[p]) * rs[p] * scale[c] + bias[c]);
    }
}

// ---------------- bf16 mma.sync GEMM: 128x128 tile, BK=64, 3-stage ----------------
// epi: 0 = +bias -> bf16 ; 1 = +bias + Res(fp32) -> fp32 ; 2 = gelu(+bias) -> bf16
__global__ __launch_bounds__(256, 2)
void gemm_bf16_kernel(const __nv_bfloat16* __restrict__ A,
                      const __nv_bfloat16* __restrict__ Bact,
                      const float* __restrict__ bias,
                      const float* __restrict__ Res,
                      void* __restrict__ Cout,
                      int K, long strideB, long strideC, int epi)
{
    extern __shared__ __nv_bfloat16 gsm[];
    unsigned int as_base = (unsigned int)__cvta_generic_to_shared(gsm);
    unsigned int bs_base = as_base + GSTG * ASZB;

    int tid = threadIdx.x;
    int m0 = blockIdx.y * BM;
    int p0 = blockIdx.x * BN;
    int b  = blockIdx.z;
    const __nv_bfloat16* Bp = Bact + (size_t)b * strideB + p0;
    const __nv_bfloat16* Ap = A + (size_t)m0 * K;

    int nk = K >> 6;   // K is a multiple of 64 here (256 or 512)

    // A: 128 rows x 64 bf16 = 1024 vec16, 4/thread: e = i*256+tid, r=e>>3, seg=(e&7)*8
    // B: 64 rows x 128 bf16 = 1024 vec16, 4/thread: e = i*256+tid, r=e>>4, seg=(e&15)*8
#pragma unroll
    for (int s = 0; s < GSTG - 1; s++) {
        if (s < nk) {
            int k0 = s * BK;
            unsigned int ao = as_base + s * ASZB;
            unsigned int bo = bs_base + s * BSZB;
#pragma unroll
            for (int i = 0; i < 4; i++) {
                int e = i * 256 + tid;
                int r = e >> 3, seg = (e & 7) * 8;
                cp_async16(ao + (r * ASTRIDE + seg) * 2, Ap + (size_t)r * K + k0 + seg);
            }
#pragma unroll
            for (int i = 0; i < 4; i++) {
                int e = i * 256 + tid;
                int r = e >> 4, seg = (e & 15) * 8;
                cp_async16(bo + (r * BSTRIDE + seg) * 2, Bp + (size_t)(k0 + r) * HW + seg);
            }
        }
        cp_commit();
    }

    int warp = tid >> 5, lane = tid & 31;
    int wm = warp >> 2;            // 0..1 : 64 m-rows
    int wn = warp & 3;             // 0..3 : 32 n-cols

    float acc[4][4][4];
#pragma unroll
    for (int i = 0; i < 4; i++)
#pragma unroll
        for (int j = 0; j < 4; j++)
#pragma unroll
            for (int q = 0; q < 4; q++) acc[i][j][q] = 0.f;

    int a_row = wm * 64 + (lane & 15);
    int a_col = (lane >> 4) * 8;
    int b_row = (lane & 15);
    int b_col = wn * 32 + (lane >> 4) * 8;

    int stg = 0;   // ring slot of stage kt
    for (int kt = 0; kt < nk; kt++) {
        cp_wait1();
        __syncthreads();

        int ps = kt + GSTG - 1;
        if (ps < nk) {
            int k0 = ps * BK;
            int pslot = stg - 1; if (pslot < 0) pslot += GSTG;   // (kt+2)%3 == (kt-1)%3
            unsigned int ao = as_base + pslot * ASZB;
            unsigned int bo = bs_base + pslot * BSZB;
#pragma unroll
            for (int i = 0; i < 4; i++) {
                int e = i * 256 + tid;
                int r = e >> 3, seg = (e & 7) * 8;
                cp_async16(ao + (r * ASTRIDE + seg) * 2, Ap + (size_t)r * K + k0 + seg);
            }
#pragma unroll
            for (int i = 0; i < 4; i++) {
                int e = i * 256 + tid;
                int r = e >> 4, seg = (e & 15) * 8;
                cp_async16(bo + (r * BSTRIDE + seg) * 2, Bp + (size_t)(k0 + r) * HW + seg);
            }
        }
        cp_commit();

        unsigned int abase = as_base + stg * ASZB;
        unsigned int bbase = bs_base + stg * BSZB;
#pragma unroll
        for (int kk = 0; kk < 4; kk++) {
            unsigned int af[4][4];
            unsigned int bfr[2][4];
#pragma unroll
            for (int i = 0; i < 4; i++)
                ldsm_x4(af[i], abase + (((a_row + i * 16) * ASTRIDE) + a_col + kk * 16) * 2);
#pragma unroll
            for (int j = 0; j < 2; j++)
                ldsm_x4_t(bfr[j], bbase + (((b_row + kk * 16) * BSTRIDE) + b_col + j * 16) * 2);
#pragma unroll
            for (int i = 0; i < 4; i++)
#pragma unroll
                for (int jn = 0; jn < 4; jn++)
                    mma_bf16(acc[i][jn], af[i], &bfr[jn >> 1][(jn & 1) * 2]);
        }

        if (++stg == GSTG) stg = 0;
    }

    int l4 = lane >> 2, l2 = (lane & 3) * 2;
#pragma unroll
    for (int i = 0; i < 4; i++) {
        int r0 = m0 + wm * 64 + i * 16 + l4;
        int r1 = r0 + 8;
        float bv0 = bias[r0], bv1 = bias[r1];
#pragma unroll
        for (int jn = 0; jn < 4; jn++) {
            int col = p0 + wn * 32 + jn * 8 + l2;
            size_t off0 = (size_t)b * strideC + (size_t)r0 * HW + col;
            size_t off1 = (size_t)b * strideC + (size_t)r1 * HW + col;
            float v0 = acc[i][jn][0] + bv0;
            float v1 = acc[i][jn][1] + bv0;
            float v2 = acc[i][jn][2] + bv1;
            float v3 = acc[i][jn][3] + bv1;
            if (epi == 1) {
                float* Cf = (float*)Cout;
                float2 q0 = *(const float2*)(Res + off0);
                float2 q1 = *(const float2*)(Res + off1);
                *(float2*)(Cf + off0) = make_float2(v0 + q0.x, v1 + q0.y);
                *(float2*)(Cf + off1) = make_float2(v2 + q1.x, v3 + q1.y);
            } else {
                if (epi == 2) {
                    v0 = gelu_f(v0); v1 = gelu_f(v1);
                    v2 = gelu_f(v2); v3 = gelu_f(v3);
                }
                __nv_bfloat16* Cb = (__nv_bfloat16*)Cout;
                *(unsigned int*)(Cb + off0) = pack_bf2(v0, v1);
                *(unsigned int*)(Cb + off1) = pack_bf2(v2, v3);
            }
        }
    }
}

// ---------------- fused proj GEMM + residual + LN2 (unchanged R7 winner) ----------------
__global__ __launch_bounds__(256, 2)
void proj_ln2_kernel(const __nv_bfloat16* __restrict__ Wp,
                     const __nv_bfloat16* __restrict__ Bact,
                     const float* __restrict__ bias,
                     const float* __restrict__ Resx,
                     const float* __restrict__ ln_s,
                     const float* __restrict__ ln_b,
                     float* __restrict__ X2,
                     __nv_bfloat16* __restrict__ Xln)
{
    extern __shared__ __nv_bfloat16 psm[];
    unsigned int as_base = (unsigned int)__cvta_generic_to_shared(psm);
    unsigned int bs_base = as_base + PSTG * PASZB;
    float* pm  = (float*)((char*)psm + PJ_RED);
    float* pq  = pm + 4 * 64;
    float* msm = pq + 4 * 64;
    float* rsm = msm + 64;

    int tid = threadIdx.x;
    int p0 = blockIdx.x * 64;
    int b  = blockIdx.z;
    const __nv_bfloat16* Bp = Bact + (size_t)b * CCH * HW + p0;

    int ar = tid >> 2, ac = (tid & 3) * 8;
    int br = tid >> 3, bc = (tid & 7) * 8;

#pragma unroll
    for (int s = 0; s < PSTG - 1; s++) {
        int k0 = s * 32;
        unsigned int ao = as_base + s * PASZB;
        unsigned int bo = bs_base + s * PBSZB;
#pragma unroll
        for (int i = 0; i < 4; i++) {
            int r = ar + i * 64;
            cp_async16(ao + (r * PASTR + ac) * 2, Wp + (size_t)r * 256 + k0 + ac);
        }
        cp_async16(bo + (br * PBSTR + bc) * 2, Bp + (size_t)(k0 + br) * HW + bc);
        cp_commit();
    }

    int warp = tid >> 5, lane = tid & 31;
    int wm = warp >> 1;
    int wn = warp & 1;

    float acc[4][4][4];
#pragma unroll
    for (int i = 0; i < 4; i++)
#pragma unroll
        for (int j = 0; j < 4; j++)
#pragma unroll
            for (int q = 0; q < 4; q++) acc[i][j][q] = 0.f;

    int a_row = wm * 64 + (lane & 15);
    int a_col = (lane >> 4) * 8;
    int b_row = (lane & 15);
    int b_col = wn * 32 + (lane >> 4) * 8;

    for (int kt = 0; kt < 8; kt++) {
        cp_wait1();
        __syncthreads();

        int ps = kt + PSTG - 1;
        if (ps < 8) {
            int k0 = ps * 32;
            unsigned int ao = as_base + (ps % PSTG) * PASZB;
            unsigned int bo = bs_base + (ps % PSTG) * PBSZB;
#pragma unroll
            for (int i = 0; i < 4; i++) {
                int r = ar + i * 64;
                cp_async16(ao + (r * PASTR + ac) * 2, Wp + (size_t)r * 256 + k0 + ac);
            }
            cp_async16(bo + (br * PBSTR + bc) * 2, Bp + (size_t)(k0 + br) * HW + bc);
        }
        cp_commit();

        unsigned int abase = as_base + (kt % PSTG) * PASZB;
        unsigned int bbase = bs_base + (kt % PSTG) * PBSZB;
#pragma unroll
        for (int kk = 0; kk < 2; kk++) {
            unsigned int af[4][4];
            unsigned int bfr[2][4];
#pragma unroll
            for (int i = 0; i < 4; i++)
                ldsm_x4(af[i], abase + (((a_row + i * 16) * PASTR) + a_col + kk * 16) * 2);
#pragma unroll
            for (int j = 0; j < 2; j++)
                ldsm_x4_t(bfr[j], bbase + (((b_row + kk * 16) * PBSTR) + b_col + j * 16) * 2);
#pragma unroll
            for (int i = 0; i < 4; i++)
#pragma unroll
                for (int jn = 0; jn < 4; jn++)
                    mma_bf16(acc[i][jn], af[i], &bfr[jn >> 1][(jn & 1) * 2]);
        }
    }

    int l4 = lane >> 2, l2 = (lane & 3) * 2;
    float s0[8], s1[8];
#pragma unroll
    for (int u = 0; u < 8; u++) { s0[u] = 0.f; s1[u] = 0.f; }

#pragma unroll
    for (int i = 0; i < 4; i++) {
        int r0 = wm * 64 + i * 16 + l4;
        int r1 = r0 + 8;
        float bv0 = bias[r0], bv1 = bias[r1];
#pragma unroll
        for (int jn = 0; jn < 4; jn++) {
            int col = p0 + wn * 32 + jn * 8 + l2;
            size_t off0 = (size_t)b * CCH * HW + (size_t)r0 * HW + col;
            size_t off1 = (size_t)b * CCH * HW + (size_t)r1 * HW + col;
            float2 q0 = *(const float2*)(Resx + off0);
            float2 q1 = *(const float2*)(Resx + off1);
            float v0 = acc[i][jn][0] + bv0 + q0.x;
            float v1 = acc[i][jn][1] + bv0 + q0.y;
            float v2 = acc[i][jn][2] + bv1 + q1.x;
            float v3 = acc[i][jn][3] + bv1 + q1.y;
            acc[i][jn][0] = v0; acc[i][jn][1] = v1;
            acc[i][jn][2] = v2; acc[i][jn][3] = v3;
            *(float2*)(X2 + off0) = make_float2(v0, v1);
            *(float2*)(X2 + off1) = make_float2(v2, v3);
            s0[jn * 2 + 0] += v0 + v2;
            s0[jn * 2 + 1] += v1 + v3;
            s1[jn * 2 + 0] += v0 * v0 + v2 * v2;
            s1[jn * 2 + 1] += v1 * v1 + v3 * v3;
        }
    }

#pragma unroll
    for (int u = 0; u < 8; u++) {
        s0[u] += __shfl_xor_sync(0xffffffffu, s0[u], 4);
        s0[u] += __shfl_xor_sync(0xffffffffu, s0[u], 8);
        s0[u] += __shfl_xor_sync(0xffffffffu, s0[u], 16);
        s1[u] += __shfl_xor_sync(0xffffffffu, s1[u], 4);
        s1[u] += __shfl_xor_sync(0xffffffffu, s1[u], 8);
        s1[u] += __shfl_xor_sync(0xffffffffu, s1[u], 16);
    }
    if (l4 == 0) {
#pragma unroll
        for (int jn = 0; jn < 4; jn++) {
            int c = wn * 32 + jn * 8 + l2;
            pm[wm * 64 + c]     = s0[jn * 2 + 0];
            pm[wm * 64 + c + 1] = s0[jn * 2 + 1];
            pq[wm * 64 + c]     = s1[jn * 2 + 0];
            pq[wm * 64 + c + 1] = s1[jn * 2 + 1];
        }
    }
    __syncthreads();
    if (tid < 64) {
        float sm_ = pm[tid] + pm[64 + tid] + pm[128 + tid] + pm[192 + tid];
        float sq_ = pq[tid] + pq[64 + tid] + pq[128 + tid] + pq[192 + tid];
        float mu  = sm_ * (1.0f / CCH);
        float var = sq_ * (1.0f / CCH) - mu * mu;
        msm[tid] = mu;
        rsm[tid] = rsqrtf(var + 1e-5f);
    }
    __syncthreads();

#pragma unroll
    for (int i = 0; i < 4; i++) {
        int r0 = wm * 64 + i * 16 + l4;
        int r1 = r0 + 8;
        float sc0 = ln_s[r0], sb0 = ln_b[r0];
        float sc1 = ln_s[r1], sb1 = ln_b[r1];
#pragma unroll
        for (int jn = 0; jn < 4; jn++) {
            int c = wn * 32 + jn * 8 + l2;
            int col = p0 + c;
            float mu0 = msm[c], r_0 = rsm[c];
            float mu1 = msm[c + 1], r_1 = rsm[c + 1];
            size_t off0 = (size_t)b * CCH * HW + (size_t)r0 * HW + col;
            size_t off1 = (size_t)b * CCH * HW + (size_t)r1 * HW + col;
            float y0 = (acc[i][jn][0] - mu0) * r_0 * sc0 + sb0;
            float y1 = (acc[i][jn][1] - mu1) * r_1 * sc0 + sb0;
            float y2 = (acc[i][jn][2] - mu0) * r_0 * sc1 + sb1;
            float y3 = (acc[i][jn][3] - mu1) * r_1 * sc1 + sb1;
            *(unsigned int*)(Xln + off0) = pack_bf2(y0, y1);
            *(unsigned int*)(Xln + off1) = pack_bf2(y2, y3);
        }
    }
}

// ---------------- tensor-core chunked attention (unchanged) ----------------
__global__ __launch_bounds__(128)
void attn_mma_kernel(const __nv_bfloat16* __restrict__ qkv, __nv_bfloat16* __restrict__ out)
{
    extern __shared__ __nv_bfloat16 ats[];
    __nv_bfloat16* QVs = ats + AT_QV;
    __nv_bfloat16* Ksm = ats + AT_K;
    __nv_bfloat16* Psm = ats + AT_P;

    unsigned int qv_base = (unsigned int)__cvta_generic_to_shared(QVs);
    unsigned int k_base  = (unsigned int)__cvta_generic_to_shared(Ksm);
    unsigned int p_base  = (unsigned int)__cvta_generic_to_shared(Psm);

    int g = blockIdx.x, b = blockIdx.y;
    int tid = threadIdx.x;
    int warp = tid >> 5, lane = tid & 31;
    const __nv_bfloat16* base = qkv + (size_t)b * 3 * CCH * HW + (size_t)g * CHUNK;

#pragma unroll
    for (int k = 0; k < 16; k++) {
        int e = k * 128 + tid;
        int c = e >> 3, seg = (e & 7) * 8;
        cp_async16(qv_base + (c * ATS + seg) * 2, base + (size_t)c * HW + seg);
        cp_async16(k_base  + (c * ATS + seg) * 2, base + (size_t)(256 + c) * HW + seg);
    }
    cp_commit();
    cp_wait0();
    __syncthreads();

    int i0 = warp * 16;
    float acc[8][4];
#pragma unroll
    for (int t = 0; t < 8; t++)
#pragma unroll
        for (int q = 0; q < 4; q++) acc[t][q] = 0.f;

    int a_c = (lane & 7) + ((lane >> 4) << 3);
    int a_m = i0 + ((lane >> 3) & 1) * 8;
    int b_c = (lane & 15);
    int b_j = (lane >> 4) * 8;

#pragma unroll
    for (int kk = 0; kk < 16; kk++) {
        unsigned int af[4];
        ldsm_x4_t(af, qv_base + (((kk * 16 + a_c) * ATS) + a_m) * 2);
#pragma unroll
        for (int jt = 0; jt < 4; jt++) {
            unsigned int bfr[4];
            ldsm_x4_t(bfr, k_base + (((kk * 16 + b_c) * ATS) + jt * 16 + b_j) * 2);
            mma_bf16(acc[jt * 2 + 0], af, &bfr[0]);
            mma_bf16(acc[jt * 2 + 1], af, &bfr[2]);
        }
    }

    {
        const float SC = 0.0625f;
#pragma unroll
        for (int t = 0; t < 8; t++)
#pragma unroll
            for (int q = 0; q < 4; q++) acc[t][q] *= SC;

        float mxA = -1e30f, mxB = -1e30f;
#pragma unroll
        for (int t = 0; t < 8; t++) {
            mxA = fmaxf(mxA, fmaxf(acc[t][0], acc[t][1]));
            mxB = fmaxf(mxB, fmaxf(acc[t][2], acc[t][3]));
        }
        mxA = fmaxf(mxA, __shfl_xor_sync(0xffffffffu, mxA, 1));
        mxA = fmaxf(mxA, __shfl_xor_sync(0xffffffffu, mxA, 2));
        mxB = fmaxf(mxB, __shfl_xor_sync(0xffffffffu, mxB, 1));
        mxB = fmaxf(mxB, __shfl_xor_sync(0xffffffffu, mxB, 2));

        float sA = 0.f, sB = 0.f;
#pragma unroll
        for (int t = 0; t < 8; t++) {
            acc[t][0] = expf(acc[t][0] - mxA); sA += acc[t][0];
            acc[t][1] = expf(acc[t][1] - mxA); sA += acc[t][1];
            acc[t][2] = expf(acc[t][2] - mxB); sB += acc[t][2];
            acc[t][3] = expf(acc[t][3] - mxB); sB += acc[t][3];
        }
        sA += __shfl_xor_sync(0xffffffffu, sA, 1);
        sA += __shfl_xor_sync(0xffffffffu, sA, 2);
        sB += __shfl_xor_sync(0xffffffffu, sB, 1);
        sB += __shfl_xor_sync(0xffffffffu, sB, 2);
        float iA = 1.0f / sA, iB = 1.0f / sB;
#pragma unroll
        for (int t = 0; t < 8; t++) {
            acc[t][0] *= iA; acc[t][1] *= iA;
            acc[t][2] *= iB; acc[t][3] *= iB;
        }
    }

    __syncthreads();

#pragma unroll
    for (int k = 0; k < 16; k++) {
        int e = k * 128 + tid;
        int c = e >> 3, seg = (e & 7) * 8;
        cp_async16(qv_base + (c * ATS + seg) * 2, base + (size_t)(512 + c) * HW + seg);
    }
    cp_commit();
    {
        int r = i0 + (lane >> 2);
#pragma unroll
        for (int t = 0; t < 8; t++) {
            int jc = t * 8 + (lane & 3) * 2;
            *(unsigned int*)(Psm + r * ATS + jc)       = pack_bf2(acc[t][0], acc[t][1]);
            *(unsigned int*)(Psm + (r + 8) * ATS + jc) = pack_bf2(acc[t][2], acc[t][3]);
        }
    }
    cp_wait0();
    __syncthreads();

    int ap_r = (lane & 15);
    int ap_k = (lane >> 4) * 8;
    int bv_n = (lane & 7) + ((lane >> 4) << 3);
    int bv_k = ((lane >> 3) & 1) * 8;

#pragma unroll
    for (int pass = 0; pass < 2; pass++) {
        int cbase = warp * 64 + pass * 32;
        float oc[4][4][4];
#pragma unroll
        for (int it = 0; it < 4; it++)
#pragma unroll
            for (int nn = 0; nn < 4; nn++)
#pragma unroll
                for (int q = 0; q < 4; q++) oc[it][nn][q] = 0.f;

#pragma unroll
        for (int kk = 0; kk < 4; kk++) {
            unsigned int ap[4][4];
#pragma unroll
            for (int it = 0; it < 4; it++)
                ldsm_x4(ap[it], p_base + (((it * 16 + ap_r) * ATS) + kk * 16 + ap_k) * 2);
            unsigned int bv[2][4];
#pragma unroll
            for (int nt = 0; nt < 2; nt++)
                ldsm_x4(bv[nt], qv_base + (((cbase + nt * 16 + bv_n) * ATS) + kk * 16 + bv_k) * 2);
#pragma unroll
            for (int it = 0; it < 4; it++)
#pragma unroll
                for (int nn = 0; nn < 4; nn++)
                    mma_bf16(oc[it][nn], ap[it], &bv[nn >> 1][(nn & 1) * 2]);
        }

#pragma unroll
        for (int it = 0; it < 4; it++) {
            int r = it * 16 + (lane >> 2);
#pragma unroll
            for (int nn = 0; nn < 4; nn++) {
                int cc = cbase + nn * 8 + (lane & 3) * 2;
                Ksm[cc * ATS + r]           = __float2bfloat16(oc[it][nn][0]);
                Ksm[(cc + 1) * ATS + r]     = __float2bfloat16(oc[it][nn][1]);
                Ksm[cc * ATS + r + 8]       = __float2bfloat16(oc[it][nn][2]);
                Ksm[(cc + 1) * ATS + r + 8] = __float2bfloat16(oc[it][nn][3]);
            }
        }
    }
    __syncthreads();

    __nv_bfloat16* op = out + (size_t)b * CCH * HW + (size_t)g * CHUNK;
#pragma unroll
    for (int k = 0; k < 16; k++) {
        int e = k * 128 + tid;
        int c = e >> 3, seg = (e & 7) * 8;
        *(uint4*)(op + (size_t)c * HW + seg) = *(uint4*)(Ksm + c * ATS + seg);
    }
}

// ---------------- vectorized depthwise 3x3 conv + bias + gelu ----------------
__global__ __launch_bounds__(256)
void dwconv_kernel(const __nv_bfloat16* __restrict__ in,
                   const float* __restrict__ w,
                   const float* __restrict__ bias,
                   __nv_bfloat16* __restrict__ out)
{
    int t = blockIdx.x * 256 + threadIdx.x;
    int px0 = t * 8;
    int x0 = px0 & 127;
    int y  = (px0 >> 7) & 127;
    int bc = px0 >> 14;
    int c  = bc & (HID - 1);
    const __nv_bfloat16* ip = in + ((size_t)bc << 14);
    const float* wp = w + c * 9;

    float v[3][10];
#pragma unroll
    for (int r = 0; r < 3; r++) {
        int yy = y + r - 1;
        if (yy < 0 || yy > 127) {
#pragma unroll
            for (int j = 0; j < 10; j++) v[r][j] = 0.f;
        } else {
            const __nv_bfloat16* rp = ip + yy * 128 + x0;
            BFV8 mid; mid.q = *(const uint4*)rp;
#pragma unroll
            for (int j = 0; j < 8; j++) v[r][j + 1] = __bfloat162float(mid.h[j]);
            v[r][0] = (x0 > 0)   ? __bfloat162float(rp[-1]) : 0.f;
            v[r][9] = (x0 < 120) ? __bfloat162float(rp[8])  : 0.f;
        }
    }

    float w0 = wp[0], w1 = wp[1], w2 = wp[2];
    float w3 = wp[3], w4 = wp[4], w5 = wp[5];
    float w6 = wp[6], w7 = wp[7], w8 = wp[8];
    float bv = bias[c];

    unsigned int res[4];
#pragma unroll
    for (int x = 0; x < 8; x += 2) {
        float o0 = bv, o1 = bv;
        o0 += w0 * v[0][x] + w1 * v[0][x + 1] + w2 * v[0][x + 2];
        o0 += w3 * v[1][x] + w4 * v[1][x + 1] + w5 * v[1][x + 2];
        o0 += w6 * v[2][x] + w7 * v[2][x + 1] + w8 * v[2][x + 2];
        o1 += w0 * v[0][x + 1] + w1 * v[0][x + 2] + w2 * v[0][x + 3];
        o1 += w3 * v[1][x + 1] + w4 * v[1][x + 2] + w5 * v[1][x + 3];
        o1 += w6 * v[2][x + 1] + w7 * v[2][x + 2] + w8 * v[2][x + 3];
        res[x >> 1] = pack_bf2(gelu_f(o0), gelu_f(o1));
    }
    *(uint4*)(out + px0) = *(uint4*)res;
}

// ---------------- launcher ----------------
extern "C" void kernel_launch(void* const* d_in, const int* in_sizes, int n_in,
                              void* d_out, int out_size)
{
    const float* x       = (const float*)d_in[0];
    const float* ln1_s   = (const float*)d_in[1];
    const float* ln1_b   = (const float*)d_in[2];
    const float* qkv_w   = (const float*)d_in[3];
    const float* qkv_b   = (const float*)d_in[4];
    const float* proj_w  = (const float*)d_in[5];
    const float* proj_b  = (const float*)d_in[6];
    const float* ln2_s   = (const float*)d_in[7];
    const float* ln2_b   = (const float*)d_in[8];
    const float* conv1_w = (const float*)d_in[9];
    const float* conv1_b = (const float*)d_in[10];
    const float* conv2_w = (const float*)d_in[11];
    const float* conv2_b = (const float*)d_in[12];
    const float* conv3_w = (const float*)d_in[13];
    const float* conv3_b = (const float*)d_in[14];
    float* outp = (float*)d_out;

    __nv_bfloat16 *xln, *qkv, *attnp, *h1, *h2, *wbf;
    float *x2;
    cudaGetSymbolAddress((void**)&xln,   g_xln);
    cudaGetSymbolAddress((void**)&qkv,   g_qkv);
    cudaGetSymbolAddress((void**)&attnp, g_attn);
    cudaGetSymbolAddress((void**)&x2,    g_x2);
    cudaGetSymbolAddress((void**)&h1,    g_h1);
    cudaGetSymbolAddress((void**)&h2,    g_h2);
    cudaGetSymbolAddress((void**)&wbf,   g_wbf);

    __nv_bfloat16* w_qkv = wbf;
    __nv_bfloat16* w_prj = w_qkv + 768 * 256;
    __nv_bfloat16* w_c1  = w_prj + 256 * 256;
    __nv_bfloat16* w_c3  = w_c1 + 512 * 256;

    cudaFuncSetAttribute(attn_mma_kernel, cudaFuncAttributeMaxDynamicSharedMemorySize, AT_SMEM_BYTES);
    cudaFuncSetAttribute(pre_kernel, cudaFuncAttributeMaxDynamicSharedMemorySize, LN_SMEM_BYTES);
    cudaFuncSetAttribute(gemm_bf16_kernel, cudaFuncAttributeMaxDynamicSharedMemorySize, GE_SMEM);
    cudaFuncSetAttribute(proj_ln2_kernel, cudaFuncAttributeMaxDynamicSharedMemorySize, PJ_SMEM);

    // 1) LN1 + weight conversion (merged)
    pre_kernel<<<4096, 256, LN_SMEM_BYTES>>>(x, ln1_s, ln1_b, xln,
                                             qkv_w, proj_w, conv1_w, conv3_w, wbf);

    // 2) QKV GEMM -> qkv bf16
    gemm_bf16_kernel<<<dim3(HW / BN, 768 / BM, BATCH), 256, GE_SMEM>>>(
        w_qkv, xln, qkv_b, nullptr, qkv, 256,
        (long)CCH * HW, (long)3 * CCH * HW, 0);

    // 3) attention -> attn bf16
    attn_mma_kernel<<<dim3(NG, BATCH), 128, AT_SMEM_BYTES>>>(qkv, attnp);

    // 4) proj GEMM + residual + LN2 -> x2 fp32, xln bf16 (fused)
    proj_ln2_kernel<<<dim3(HW / 64, 1, BATCH), 256, PJ_SMEM>>>(
        w_prj, attnp, proj_b, x, ln2_s, ln2_b, x2, xln);

    // 5) conv1 (1x1) + gelu -> h1 bf16
    gemm_bf16_kernel<<<dim3(HW / BN, 512 / BM, BATCH), 256, GE_SMEM>>>(
        w_c1, xln, conv1_b, nullptr, h1, 256,
        (long)CCH * HW, (long)HID * HW, 2);

    // 6) depthwise 3x3 + gelu -> h2 bf16 (vectorized, 8 px/thread)
    dwconv_kernel<<<BATCH * HID * HW / (256 * 8), 256>>>(h1, conv2_w, conv2_b, h2);

    // 7) conv3 (1x1) + residual(x2) -> out fp32
    gemm_bf16_kernel<<<dim3(HW / BN, 256 / BM, BATCH), 256, GE_SMEM>>>(
        w_c3, h2, conv3_b, x2, outp, 512,
        (long)HID * HW, (long)CCH * HW, 1);
}

// round 11
// speedup vs baseline: 1.2847x; 1.0193x over previous
#include <cuda_runtime.h>
#include <cuda_bf16.h>
#include <cstdint>
#include <cstddef>
#include <math.h>

// Problem constants
#define BATCH 8
#define CCH   256
#define HW    16384
#define HID   512
#define CHUNK 64
#define NG    (HW / CHUNK)

// Generic GEMM tiling: 128x128 CTA, 8 warps x (64x32), BK=64, 3-stage pipeline
#define BM 128
#define BN 128
#define BK 64
#define ASTRIDE 72
#define BSTRIDE 136
#define ASZB (BM * ASTRIDE * 2)      // 18432
#define BSZB (BK * BSTRIDE * 2)      // 17408
#define GSTG 3
#define GE_SMEM (GSTG * (ASZB + BSZB))   // 107520

// fused attn+proj+LN2 smem layout (bytes), bf16 row stride ATS=72
#define ATS 72
#define FP_P    0                 // P  : 64  x 72 x2 =  9216
#define FP_QV   9216              // Q/V: 256 x 72 x2 = 36864
#define FP_K    46080             // K/O: 256 x 72 x2 = 36864
#define FP_STAT 82944             // pm 1024 + pq 1024 + msm 256 + rsm 256
#define FP_SMEM (82944 + 2560)    // 85504
// proj A (weights) staging: 2 stages x 256 rows x stride 40 bf16 = 20480 B each,
// placed in the dead P+QV region [0, 46080)
#define FP_A0   0
#define FP_A1   20480
#define PASTR   40

// LN smem
#define LN_SMEM_BYTES (256 * 65 * 4 + 128 * 4)

// ---------------- scratch ----------------
__device__ __nv_bfloat16 g_xln [BATCH * CCH * HW];
__device__ __nv_bfloat16 g_qkv [BATCH * 3 * CCH * HW];
__device__ float         g_x2  [BATCH * CCH * HW];
__device__ __nv_bfloat16 g_h1  [BATCH * HID * HW];
__device__ __nv_bfloat16 g_h2  [BATCH * HID * HW];
__device__ __nv_bfloat16 g_wbf [768*256 + 256*256 + 512*256 + 256*512];

__device__ __forceinline__ float gelu_f(float v) {
    return 0.5f * v * (1.0f + erff(v * 0.70710678118654752f));
}

union BF2U { __nv_bfloat162 h; unsigned int u; };
__device__ __forceinline__ unsigned int pack_bf2(float a, float b) {
    BF2U t; t.h = __floats2bfloat162_rn(a, b); return t.u;
}
union BFV8 { uint4 q; __nv_bfloat16 h[8]; };

// ---------------- helpers ----------------
__device__ __forceinline__ void ldsm_x4(unsigned int* r, unsigned int addr) {
    asm volatile("ldmatrix.sync.aligned.m8n8.x4.shared.b16 {%0,%1,%2,%3}, [%4];"
                 : "=r"(r[0]), "=r"(r[1]), "=r"(r[2]), "=r"(r[3]) : "r"(addr));
}
__device__ __forceinline__ void ldsm_x4_t(unsigned int* r, unsigned int addr) {
    asm volatile("ldmatrix.sync.aligned.m8n8.x4.trans.shared.b16 {%0,%1,%2,%3}, [%4];"
                 : "=r"(r[0]), "=r"(r[1]), "=r"(r[2]), "=r"(r[3]) : "r"(addr));
}
__device__ __forceinline__ void mma_bf16(float* d, const unsigned int* a, const unsigned int* b) {
    asm volatile("mma.sync.aligned.m16n8k16.row.col.f32.bf16.bf16.f32 "
                 "{%0,%1,%2,%3}, {%4,%5,%6,%7}, {%8,%9}, {%0,%1,%2,%3};"
                 : "+f"(d[0]), "+f"(d[1]), "+f"(d[2]), "+f"(d[3])
                 : "r"(a[0]), "r"(a[1]), "r"(a[2]), "r"(a[3]), "r"(b[0]), "r"(b[1]));
}
__device__ __forceinline__ void cp_async16(unsigned int dst, const void* src) {
    asm volatile("cp.async.cg.shared.global [%0], [%1], 16;" :: "r"(dst), "l"(src));
}
__device__ __forceinline__ void cp_commit() {
    asm volatile("cp.async.commit_group;" ::: "memory");
}
__device__ __forceinline__ void cp_wait0() {
    asm volatile("cp.async.wait_group 0;" ::: "memory");
}
__device__ __forceinline__ void cp_wait1() {
    asm volatile("cp.async.wait_group 1;" ::: "memory");
}

// ---------------- merged LN1 + weight conversion ----------------
__global__ __launch_bounds__(256)
void pre_kernel(const float* __restrict__ in,
                const float* __restrict__ scale,
                const float* __restrict__ bias,
                __nv_bfloat16* __restrict__ out,
                const float* __restrict__ s0, const float* __restrict__ s1,
                const float* __restrict__ s2, const float* __restrict__ s3,
                __nv_bfloat16* __restrict__ wdst)
{
    int tid = threadIdx.x;
    if (blockIdx.x >= 2048) {
        int i = (blockIdx.x - 2048) * 256 + tid;
        const float* s; int off;
        if (i < 196608)      { s = s0; off = i; }
        else if (i < 262144) { s = s1; off = i - 196608; }
        else if (i < 393216) { s = s2; off = i - 262144; }
        else                 { s = s3; off = i - 393216; }
        wdst[i] = __float2bfloat16(s[off]);
        return;
    }

    extern __shared__ float lns[];
    float* ts  = lns;
    float* mus = lns + 256 * 65;
    float* rs  = mus + 64;

    int bp = blockIdx.x;
    int b  = bp >> 8;
    int p0 = (bp & 255) * 64;
    const float* ip = in + (size_t)b * CCH * HW + p0;

#pragma unroll
    for (int k = 0; k < 64; k++) {
        int e = k * 256 + tid;
        int c = e >> 6, p = e & 63;
        ts[c * 65 + p] = ip[(size_t)c * HW + p];
    }
    __syncthreads();

    {
        int tq = tid & 3, pp = tid >> 2;
        float s = 0.f, s2 = 0.f;
#pragma unroll 16
        for (int j = 0; j < 64; j++) {
            float v = ts[(tq + 4 * j) * 65 + pp];
            s += v; s2 += v * v;
        }
        s  += __shfl_xor_sync(0xffffffffu, s, 1);
        s  += __shfl_xor_sync(0xffffffffu, s, 2);
        s2 += __shfl_xor_sync(0xffffffffu, s2, 1);
        s2 += __shfl_xor_sync(0xffffffffu, s2, 2);
        float mu  = s * (1.0f / CCH);
        float var = s2 * (1.0f / CCH) - mu * mu;
        if (tq == 0) { mus[pp] = mu; rs[pp] = rsqrtf(var + 1e-5f); }
    }
    __syncthreads();

    __nv_bfloat16* op = out + (size_t)b * CCH * HW + p0;
#pragma unroll
    for (int k = 0; k < 64; k++) {
        int e = k * 256 + tid;
        int c = e >> 6, p = e & 63;
        float v = ts[c * 65 + p];
        op[(size_t)c * HW + p] = __float2bfloat16((v - mus[p]) * rs[p] * scale[c] + bias[c]);
    }
}

// ---------------- bf16 mma.sync GEMM: 128x128, BK=64, 3-stage (R10) ----------------
__global__ __launch_bounds__(256, 2)
void gemm_bf16_kernel(const __nv_bfloat16* __restrict__ A,
                      const __nv_bfloat16* __restrict__ Bact,
                      const float* __restrict__ bias,
                      const float* __restrict__ Res,
                      void* __restrict__ Cout,
                      int K, long strideB, long strideC, int epi)
{
    extern __shared__ __nv_bfloat16 gsm[];
    unsigned int as_base = (unsigned int)__cvta_generic_to_shared(gsm);
    unsigned int bs_base = as_base + GSTG * ASZB;

    int tid = threadIdx.x;
    int m0 = blockIdx.y * BM;
    int p0 = blockIdx.x * BN;
    int b  = blockIdx.z;
    const __nv_bfloat16* Bp = Bact + (size_t)b * strideB + p0;
    const __nv_bfloat16* Ap = A + (size_t)m0 * K;

    int nk = K >> 6;

#pragma unroll
    for (int s = 0; s < GSTG - 1; s++) {
        if (s < nk) {
            int k0 = s * BK;
            unsigned int ao = as_base + s * ASZB;
            unsigned int bo = bs_base + s * BSZB;
#pragma unroll
            for (int i = 0; i < 4; i++) {
                int e = i * 256 + tid;
                int r = e >> 3, seg = (e & 7) * 8;
                cp_async16(ao + (r * ASTRIDE + seg) * 2, Ap + (size_t)r * K + k0 + seg);
            }
#pragma unroll
            for (int i = 0; i < 4; i++) {
                int e = i * 256 + tid;
                int r = e >> 4, seg = (e & 15) * 8;
                cp_async16(bo + (r * BSTRIDE + seg) * 2, Bp + (size_t)(k0 + r) * HW + seg);
            }
        }
        cp_commit();
    }

    int warp = tid >> 5, lane = tid & 31;
    int wm = warp >> 2;
    int wn = warp & 3;

    float acc[4][4][4];
#pragma unroll
    for (int i = 0; i < 4; i++)
#pragma unroll
        for (int j = 0; j < 4; j++)
#pragma unroll
            for (int q = 0; q < 4; q++) acc[i][j][q] = 0.f;

    int a_row = wm * 64 + (lane & 15);
    int a_col = (lane >> 4) * 8;
    int b_row = (lane & 15);
    int b_col = wn * 32 + (lane >> 4) * 8;

    int stg = 0;
    for (int kt = 0; kt < nk; kt++) {
        cp_wait1();
        __syncthreads();

        int ps = kt + GSTG - 1;
        if (ps < nk) {
            int k0 = ps * BK;
            int pslot = stg - 1; if (pslot < 0) pslot += GSTG;
            unsigned int ao = as_base + pslot * ASZB;
            unsigned int bo = bs_base + pslot * BSZB;
#pragma unroll
            for (int i = 0; i < 4; i++) {
                int e = i * 256 + tid;
                int r = e >> 3, seg = (e & 7) * 8;
                cp_async16(ao + (r * ASTRIDE + seg) * 2, Ap + (size_t)r * K + k0 + seg);
            }
#pragma unroll
            for (int i = 0; i < 4; i++) {
                int e = i * 256 + tid;
                int r = e >> 4, seg = (e & 15) * 8;
                cp_async16(bo + (r * BSTRIDE + seg) * 2, Bp + (size_t)(k0 + r) * HW + seg);
            }
        }
        cp_commit();

        unsigned int abase = as_base + stg * ASZB;
        unsigned int bbase = bs_base + stg * BSZB;
#pragma unroll
        for (int kk = 0; kk < 4; kk++) {
            unsigned int af[4][4];
            unsigned int bfr[2][4];
#pragma unroll
            for (int i = 0; i < 4; i++)
                ldsm_x4(af[i], abase + (((a_row + i * 16) * ASTRIDE) + a_col + kk * 16) * 2);
#pragma unroll
            for (int j = 0; j < 2; j++)
                ldsm_x4_t(bfr[j], bbase + (((b_row + kk * 16) * BSTRIDE) + b_col + j * 16) * 2);
#pragma unroll
            for (int i = 0; i < 4; i++)
#pragma unroll
                for (int jn = 0; jn < 4; jn++)
                    mma_bf16(acc[i][jn], af[i], &bfr[jn >> 1][(jn & 1) * 2]);
        }

        if (++stg == GSTG) stg = 0;
    }

    int l4 = lane >> 2, l2 = (lane & 3) * 2;
#pragma unroll
    for (int i = 0; i < 4; i++) {
        int r0 = m0 + wm * 64 + i * 16 + l4;
        int r1 = r0 + 8;
        float bv0 = bias[r0], bv1 = bias[r1];
#pragma unroll
        for (int jn = 0; jn < 4; jn++) {
            int col = p0 + wn * 32 + jn * 8 + l2;
            size_t off0 = (size_t)b * strideC + (size_t)r0 * HW + col;
            size_t off1 = (size_t)b * strideC + (size_t)r1 * HW + col;
            float v0 = acc[i][jn][0] + bv0;
            float v1 = acc[i][jn][1] + bv0;
            float v2 = acc[i][jn][2] + bv1;
            float v3 = acc[i][jn][3] + bv1;
            if (epi == 1) {
                float* Cf = (float*)Cout;
                float2 q0 = *(const float2*)(Res + off0);
                float2 q1 = *(const float2*)(Res + off1);
                *(float2*)(Cf + off0) = make_float2(v0 + q0.x, v1 + q0.y);
                *(float2*)(Cf + off1) = make_float2(v2 + q1.x, v3 + q1.y);
            } else {
                if (epi == 2) {
                    v0 = gelu_f(v0); v1 = gelu_f(v1);
                    v2 = gelu_f(v2); v3 = gelu_f(v3);
                }
                __nv_bfloat16* Cb = (__nv_bfloat16*)Cout;
                *(unsigned int*)(Cb + off0) = pack_bf2(v0, v1);
                *(unsigned int*)(Cb + off1) = pack_bf2(v2, v3);
            }
        }
    }
}

// ---------------- FUSED attention + proj + residual + LN2 ----------------
// One block (128 thr, 4 warps) per (b, g). Computes O = softmax(Q^T K / 16) V^T in smem,
// then x2 = W_proj @ O + proj_b + x and xln = LN_c(x2), writing both to gmem.
__global__ __launch_bounds__(128)
void attn_proj_kernel(const __nv_bfloat16* __restrict__ qkv,
                      const __nv_bfloat16* __restrict__ Wp,
                      const float* __restrict__ pbias,
                      const float* __restrict__ Resx,
                      const float* __restrict__ ln_s,
                      const float* __restrict__ ln_b,
                      float* __restrict__ X2,
                      __nv_bfloat16* __restrict__ Xln)
{
    extern __shared__ __nv_bfloat16 fsm[];
    unsigned int sbase   = (unsigned int)__cvta_generic_to_shared(fsm);
    unsigned int p_base  = sbase + FP_P;
    unsigned int qv_base = sbase + FP_QV;
    unsigned int k_base  = sbase + FP_K;
    __nv_bfloat16* Psm = fsm + FP_P / 2;
    __nv_bfloat16* Ksm = fsm + FP_K / 2;
    float* pm  = (float*)((char*)fsm + FP_STAT);   // [4][64]
    float* pq  = pm + 4 * 64;                      // [4][64]
    float* msm = pq + 4 * 64;                      // [64]
    float* rsm = msm + 64;                         // [64]

    int g = blockIdx.x, b = blockIdx.y;
    int tid = threadIdx.x;
    int warp = tid >> 5, lane = tid & 31;
    const __nv_bfloat16* base = qkv + (size_t)b * 3 * CCH * HW + (size_t)g * CHUNK;

    // ---- phase 1: load Q, K ----
#pragma unroll
    for (int k = 0; k < 16; k++) {
        int e = k * 128 + tid;
        int c = e >> 3, seg = (e & 7) * 8;
        cp_async16(qv_base + (c * ATS + seg) * 2, base + (size_t)c * HW + seg);
        cp_async16(k_base  + (c * ATS + seg) * 2, base + (size_t)(256 + c) * HW + seg);
    }
    cp_commit();
    cp_wait0();
    __syncthreads();

    // ---- S = scale * Q^T K ----
    int i0 = warp * 16;
    float sacc[8][4];
#pragma unroll
    for (int t = 0; t < 8; t++)
#pragma unroll
        for (int q = 0; q < 4; q++) sacc[t][q] = 0.f;

    int a_c = (lane & 7) + ((lane >> 4) << 3);
    int a_m = i0 + ((lane >> 3) & 1) * 8;
    int b_c = (lane & 15);
    int b_j = (lane >> 4) * 8;

#pragma unroll
    for (int kk = 0; kk < 16; kk++) {
        unsigned int af[4];
        ldsm_x4_t(af, qv_base + (((kk * 16 + a_c) * ATS) + a_m) * 2);
#pragma unroll
        for (int jt = 0; jt < 4; jt++) {
            unsigned int bfr[4];
            ldsm_x4_t(bfr, k_base + (((kk * 16 + b_c) * ATS) + jt * 16 + b_j) * 2);
            mma_bf16(sacc[jt * 2 + 0], af, &bfr[0]);
            mma_bf16(sacc[jt * 2 + 1], af, &bfr[2]);
        }
    }

    // ---- softmax ----
    {
        const float SC = 0.0625f;
#pragma unroll
        for (int t = 0; t < 8; t++)
#pragma unroll
            for (int q = 0; q < 4; q++) sacc[t][q] *= SC;

        float mxA = -1e30f, mxB = -1e30f;
#pragma unroll
        for (int t = 0; t < 8; t++) {
            mxA = fmaxf(mxA, fmaxf(sacc[t][0], sacc[t][1]));
            mxB = fmaxf(mxB, fmaxf(sacc[t][2], sacc[t][3]));
        }
        mxA = fmaxf(mxA, __shfl_xor_sync(0xffffffffu, mxA, 1));
        mxA = fmaxf(mxA, __shfl_xor_sync(0xffffffffu, mxA, 2));
        mxB = fmaxf(mxB, __shfl_xor_sync(0xffffffffu, mxB, 1));
        mxB = fmaxf(mxB, __shfl_xor_sync(0xffffffffu, mxB, 2));

        float sA = 0.f, sB = 0.f;
#pragma unroll
        for (int t = 0; t < 8; t++) {
            sacc[t][0] = expf(sacc[t][0] - mxA); sA += sacc[t][0];
            sacc[t][1] = expf(sacc[t][1] - mxA); sA += sacc[t][1];
            sacc[t][2] = expf(sacc[t][2] - mxB); sB += sacc[t][2];
            sacc[t][3] = expf(sacc[t][3] - mxB); sB += sacc[t][3];
        }
        sA += __shfl_xor_sync(0xffffffffu, sA, 1);
        sA += __shfl_xor_sync(0xffffffffu, sA, 2);
        sB += __shfl_xor_sync(0xffffffffu, sB, 1);
        sB += __shfl_xor_sync(0xffffffffu, sB, 2);
        float iA = 1.0f / sA, iB = 1.0f / sB;
#pragma unroll
        for (int t = 0; t < 8; t++) {
            sacc[t][0] *= iA; sacc[t][1] *= iA;
            sacc[t][2] *= iB; sacc[t][3] *= iB;
        }
    }

    __syncthreads();   // Q dead, K dead

    // ---- load V into QV; store P ----
#pragma unroll
    for (int k = 0; k < 16; k++) {
        int e = k * 128 + tid;
        int c = e >> 3, seg = (e & 7) * 8;
        cp_async16(qv_base + (c * ATS + seg) * 2, base + (size_t)(512 + c) * HW + seg);
    }
    cp_commit();
    {
        int r = i0 + (lane >> 2);
#pragma unroll
        for (int t = 0; t < 8; t++) {
            int jc = t * 8 + (lane & 3) * 2;
            *(unsigned int*)(Psm + r * ATS + jc)       = pack_bf2(sacc[t][0], sacc[t][1]);
            *(unsigned int*)(Psm + (r + 8) * ATS + jc) = pack_bf2(sacc[t][2], sacc[t][3]);
        }
    }
    cp_wait0();
    __syncthreads();

    // ---- O^T = P @ V^T, write O into Ksm [c][t] ----
    {
        int ap_r = (lane & 15);
        int ap_k = (lane >> 4) * 8;
        int bv_n = (lane & 7) + ((lane >> 4) << 3);
        int bv_k = ((lane >> 3) & 1) * 8;

#pragma unroll
        for (int pass = 0; pass < 2; pass++) {
            int cbase = warp * 64 + pass * 32;
            float oc[4][4][4];
#pragma unroll
            for (int it = 0; it < 4; it++)
#pragma unroll
                for (int nn = 0; nn < 4; nn++)
#pragma unroll
                    for (int q = 0; q < 4; q++) oc[it][nn][q] = 0.f;

#pragma unroll
            for (int kk = 0; kk < 4; kk++) {
                unsigned int ap[4][4];
#pragma unroll
                for (int it = 0; it < 4; it++)
                    ldsm_x4(ap[it], p_base + (((it * 16 + ap_r) * ATS) + kk * 16 + ap_k) * 2);
                unsigned int bv[2][4];
#pragma unroll
                for (int nt = 0; nt < 2; nt++)
                    ldsm_x4(bv[nt], qv_base + (((cbase + nt * 16 + bv_n) * ATS) + kk * 16 + bv_k) * 2);
#pragma unroll
                for (int it = 0; it < 4; it++)
#pragma unroll
                    for (int nn = 0; nn < 4; nn++)
                        mma_bf16(oc[it][nn], ap[it], &bv[nn >> 1][(nn & 1) * 2]);
            }

#pragma unroll
            for (int it = 0; it < 4; it++) {
                int r = it * 16 + (lane >> 2);
#pragma unroll
                for (int nn = 0; nn < 4; nn++) {
                    int cc = cbase + nn * 8 + (lane & 3) * 2;
                    Ksm[cc * ATS + r]           = __float2bfloat16(oc[it][nn][0]);
                    Ksm[(cc + 1) * ATS + r]     = __float2bfloat16(oc[it][nn][1]);
                    Ksm[cc * ATS + r + 8]       = __float2bfloat16(oc[it][nn][2]);
                    Ksm[(cc + 1) * ATS + r + 8] = __float2bfloat16(oc[it][nn][3]);
                }
            }
        }
    }
    __syncthreads();   // O complete; P and QV dead -> A staging region free

    // ---- phase 3: proj GEMM. M=256 (warp owns 64 rows), N=64, K=256 in 8 chunks ----
    // A = Wp streamed into smem [0,46080) 2-stage stride PASTR=40; B = O in Ksm (k-major)
    float acc[4][8][4];
#pragma unroll
    for (int i = 0; i < 4; i++)
#pragma unroll
        for (int j = 0; j < 8; j++)
#pragma unroll
            for (int q = 0; q < 4; q++) acc[i][j][q] = 0.f;

    // prologue: chunk 0 -> stage 0
#pragma unroll
    for (int i = 0; i < 8; i++) {
        int e = i * 128 + tid;
        int r = e >> 2, seg = (e & 3) * 8;
        cp_async16(sbase + FP_A0 + (r * PASTR + seg) * 2, Wp + (size_t)r * 256 + seg);
    }
    cp_commit();

    int pa_r = (lane & 15);
    int pa_c = (lane >> 4) * 8;
    int pb_r = (lane & 15);
    int pb_c = (lane >> 4) * 8;

    for (int kt = 0; kt < 8; kt++) {
        cp_wait0();
        __syncthreads();

        if (kt + 1 < 8) {
            int k0 = (kt + 1) * 32;
            unsigned int ao = sbase + (((kt + 1) & 1) ? FP_A1 : FP_A0);
#pragma unroll
            for (int i = 0; i < 8; i++) {
                int e = i * 128 + tid;
                int r = e >> 2, seg = (e & 3) * 8;
                cp_async16(ao + (r * PASTR + seg) * 2, Wp + (size_t)r * 256 + k0 + seg);
            }
        }
        cp_commit();

        unsigned int abase = sbase + ((kt & 1) ? FP_A1 : FP_A0);
#pragma unroll
        for (int kk = 0; kk < 2; kk++) {
            unsigned int af[4][4];
            unsigned int bfr[4][4];
#pragma unroll
            for (int i = 0; i < 4; i++)
                ldsm_x4(af[i], abase + (((warp * 64 + i * 16 + pa_r) * PASTR) + pa_c + kk * 16) * 2);
#pragma unroll
            for (int j = 0; j < 4; j++)
                ldsm_x4_t(bfr[j], k_base + (((kt * 32 + kk * 16 + pb_r) * ATS) + j * 16 + pb_c) * 2);
#pragma unroll
            for (int i = 0; i < 4; i++)
#pragma unroll
                for (int jn = 0; jn < 8; jn++)
                    mma_bf16(acc[i][jn], af[i], &bfr[jn >> 1][(jn & 1) * 2]);
        }
    }

    // ---- phase 4: epilogue: +bias +x -> x2; stats; LN2 -> xln ----
    int l4 = lane >> 2, l2 = (lane & 3) * 2;
    int pcol = g * CHUNK;
    size_t boff = (size_t)b * CCH * HW;

    float s0[16], s1[16];
#pragma unroll
    for (int u = 0; u < 16; u++) { s0[u] = 0.f; s1[u] = 0.f; }

#pragma unroll
    for (int i = 0; i < 4; i++) {
        int r0 = warp * 64 + i * 16 + l4;
        int r1 = r0 + 8;
        float bv0 = pbias[r0], bv1 = pbias[r1];
#pragma unroll
        for (int jn = 0; jn < 8; jn++) {
            int col = pcol + jn * 8 + l2;
            size_t off0 = boff + (size_t)r0 * HW + col;
            size_t off1 = boff + (size_t)r1 * HW + col;
            float2 q0 = *(const float2*)(Resx + off0);
            float2 q1 = *(const float2*)(Resx + off1);
            float v0 = acc[i][jn][0] + bv0 + q0.x;
            float v1 = acc[i][jn][1] + bv0 + q0.y;
            float v2 = acc[i][jn][2] + bv1 + q1.x;
            float v3 = acc[i][jn][3] + bv1 + q1.y;
            acc[i][jn][0] = v0; acc[i][jn][1] = v1;
            acc[i][jn][2] = v2; acc[i][jn][3] = v3;
            *(float2*)(X2 + off0) = make_float2(v0, v1);
            *(float2*)(X2 + off1) = make_float2(v2, v3);
            s0[jn * 2 + 0] += v0 + v2;
            s0[jn * 2 + 1] += v1 + v3;
            s1[jn * 2 + 0] += v0 * v0 + v2 * v2;
            s1[jn * 2 + 1] += v1 * v1 + v3 * v3;
        }
    }

#pragma unroll
    for (int u = 0; u < 16; u++) {
        s0[u] += __shfl_xor_sync(0xffffffffu, s0[u], 4);
        s0[u] += __shfl_xor_sync(0xffffffffu, s0[u], 8);
        s0[u] += __shfl_xor_sync(0xffffffffu, s0[u], 16);
        s1[u] += __shfl_xor_sync(0xffffffffu, s1[u], 4);
        s1[u] += __shfl_xor_sync(0xffffffffu, s1[u], 8);
        s1[u] += __shfl_xor_sync(0xffffffffu, s1[u], 16);
    }
    if (l4 == 0) {
#pragma unroll
        for (int jn = 0; jn < 8; jn++) {
            int c = jn * 8 + (lane & 3) * 2;
            pm[warp * 64 + c]     = s0[jn * 2 + 0];
            pm[warp * 64 + c + 1] = s0[jn * 2 + 1];
            pq[warp * 64 + c]     = s1[jn * 2 + 0];
            pq[warp * 64 + c + 1] = s1[jn * 2 + 1];
        }
    }
    __syncthreads();
    if (tid < 64) {
        float sm_ = pm[tid] + pm[64 + tid] + pm[128 + tid] + pm[192 + tid];
        float sq_ = pq[tid] + pq[64 + tid] + pq[128 + tid] + pq[192 + tid];
        float mu  = sm_ * (1.0f / CCH);
        float var = sq_ * (1.0f / CCH) - mu * mu;
        msm[tid] = mu;
        rsm[tid] = rsqrtf(var + 1e-5f);
    }
    __syncthreads();

#pragma unroll
    for (int i = 0; i < 4; i++) {
        int r0 = warp * 64 + i * 16 + l4;
        int r1 = r0 + 8;
        float sc0 = ln_s[r0], sb0 = ln_b[r0];
        float sc1 = ln_s[r1], sb1 = ln_b[r1];
#pragma unroll
        for (int jn = 0; jn < 8; jn++) {
            int c = jn * 8 + l2;
            int col = pcol + c;
            float mu0 = msm[c], r_0 = rsm[c];
            float mu1 = msm[c + 1], r_1 = rsm[c + 1];
            size_t off0 = boff + (size_t)r0 * HW + col;
            size_t off1 = boff + (size_t)r1 * HW + col;
            float y0 = (acc[i][jn][0] - mu0) * r_0 * sc0 + sb0;
            float y1 = (acc[i][jn][1] - mu1) * r_1 * sc0 + sb0;
            float y2 = (acc[i][jn][2] - mu0) * r_0 * sc1 + sb1;
            float y3 = (acc[i][jn][3] - mu1) * r_1 * sc1 + sb1;
            *(unsigned int*)(Xln + off0) = pack_bf2(y0, y1);
            *(unsigned int*)(Xln + off1) = pack_bf2(y2, y3);
        }
    }
}

// ---------------- vectorized depthwise 3x3 conv + bias + gelu ----------------
__global__ __launch_bounds__(256)
void dwconv_kernel(const __nv_bfloat16* __restrict__ in,
                   const float* __restrict__ w,
                   const float* __restrict__ bias,
                   __nv_bfloat16* __restrict__ out)
{
    int t = blockIdx.x * 256 + threadIdx.x;
    int px0 = t * 8;
    int x0 = px0 & 127;
    int y  = (px0 >> 7) & 127;
    int bc = px0 >> 14;
    int c  = bc & (HID - 1);
    const __nv_bfloat16* ip = in + ((size_t)bc << 14);
    const float* wp = w + c * 9;

    float v[3][10];
#pragma unroll
    for (int r = 0; r < 3; r++) {
        int yy = y + r - 1;
        if (yy < 0 || yy > 127) {
#pragma unroll
            for (int j = 0; j < 10; j++) v[r][j] = 0.f;
        } else {
            const __nv_bfloat16* rp = ip + yy * 128 + x0;
            BFV8 mid; mid.q = *(const uint4*)rp;
#pragma unroll
            for (int j = 0; j < 8; j++) v[r][j + 1] = __bfloat162float(mid.h[j]);
            v[r][0] = (x0 > 0)   ? __bfloat162float(rp[-1]) : 0.f;
            v[r][9] = (x0 < 120) ? __bfloat162float(rp[8])  : 0.f;
        }
    }

    float w0 = wp[0], w1 = wp[1], w2 = wp[2];
    float w3 = wp[3], w4 = wp[4], w5 = wp[5];
    float w6 = wp[6], w7 = wp[7], w8 = wp[8];
    float bv = bias[c];

    unsigned int res[4];
#pragma unroll
    for (int x = 0; x < 8; x += 2) {
        float o0 = bv, o1 = bv;
        o0 += w0 * v[0][x] + w1 * v[0][x + 1] + w2 * v[0][x + 2];
        o0 += w3 * v[1][x] + w4 * v[1][x + 1] + w5 * v[1][x + 2];
        o0 += w6 * v[2][x] + w7 * v[2][x + 1] + w8 * v[2][x + 2];
        o1 += w0 * v[0][x + 1] + w1 * v[0][x + 2] + w2 * v[0][x + 3];
        o1 += w3 * v[1][x + 1] + w4 * v[1][x + 2] + w5 * v[1][x + 3];
        o1 += w6 * v[2][x + 1] + w7 * v[2][x + 2] + w8 * v[2][x + 3];
        res[x >> 1] = pack_bf2(gelu_f(o0), gelu_f(o1));
    }
    *(uint4*)(out + px0) = *(uint4*)res;
}

// ---------------- launcher ----------------
extern "C" void kernel_launch(void* const* d_in, const int* in_sizes, int n_in,
                              void* d_out, int out_size)
{
    const float* x       = (const float*)d_in[0];
    const float* ln1_s   = (const float*)d_in[1];
    const float* ln1_b   = (const float*)d_in[2];
    const float* qkv_w   = (const float*)d_in[3];
    const float* qkv_b   = (const float*)d_in[4];
    const float* proj_w  = (const float*)d_in[5];
    const float* proj_b  = (const float*)d_in[6];
    const float* ln2_s   = (const float*)d_in[7];
    const float* ln2_b   = (const float*)d_in[8];
    const float* conv1_w = (const float*)d_in[9];
    const float* conv1_b = (const float*)d_in[10];
    const float* conv2_w = (const float*)d_in[11];
    const float* conv2_b = (const float*)d_in[12];
    const float* conv3_w = (const float*)d_in[13];
    const float* conv3_b = (const float*)d_in[14];
    float* outp = (float*)d_out;

    __nv_bfloat16 *xln, *qkv, *h1, *h2, *wbf;
    float *x2;
    cudaGetSymbolAddress((void**)&xln,   g_xln);
    cudaGetSymbolAddress((void**)&qkv,   g_qkv);
    cudaGetSymbolAddress((void**)&x2,    g_x2);
    cudaGetSymbolAddress((void**)&h1,    g_h1);
    cudaGetSymbolAddress((void**)&h2,    g_h2);
    cudaGetSymbolAddress((void**)&wbf,   g_wbf);

    __nv_bfloat16* w_qkv = wbf;
    __nv_bfloat16* w_prj = w_qkv + 768 * 256;
    __nv_bfloat16* w_c1  = w_prj + 256 * 256;
    __nv_bfloat16* w_c3  = w_c1 + 512 * 256;

    cudaFuncSetAttribute(attn_proj_kernel, cudaFuncAttributeMaxDynamicSharedMemorySize, FP_SMEM);
    cudaFuncSetAttribute(pre_kernel, cudaFuncAttributeMaxDynamicSharedMemorySize, LN_SMEM_BYTES);
    cudaFuncSetAttribute(gemm_bf16_kernel, cudaFuncAttributeMaxDynamicSharedMemorySize, GE_SMEM);

    // 1) LN1 + weight conversion (merged)
    pre_kernel<<<4096, 256, LN_SMEM_BYTES>>>(x, ln1_s, ln1_b, xln,
                                             qkv_w, proj_w, conv1_w, conv3_w, wbf);

    // 2) QKV GEMM -> qkv bf16
    gemm_bf16_kernel<<<dim3(HW / BN, 768 / BM, BATCH), 256, GE_SMEM>>>(
        w_qkv, xln, qkv_b, nullptr, qkv, 256,
        (long)CCH * HW, (long)3 * CCH * HW, 0);

    // 3) FUSED attention + proj + residual + LN2 -> x2 fp32, xln bf16
    attn_proj_kernel<<<dim3(NG, BATCH), 128, FP_SMEM>>>(
        qkv, w_prj, proj_b, x, ln2_s, ln2_b, x2, xln);

    // 4) conv1 (1x1) + gelu -> h1 bf16
    gemm_bf16_kernel<<<dim3(HW / BN, 512 / BM, BATCH), 256, GE_SMEM>>>(
        w_c1, xln, conv1_b, nullptr, h1, 256,
        (long)CCH * HW, (long)HID * HW, 2);

    // 5) depthwise 3x3 + gelu -> h2 bf16
    dwconv_kernel<<<BATCH * HID * HW / (256 * 8), 256>>>(h1, conv2_w, conv2_b, h2);

    // 6) conv3 (1x1) + residual(x2) -> out fp32
    gemm_bf16_kernel<<<dim3(HW / BN, 256 / BM, BATCH), 256, GE_SMEM>>>(
        w_c3, h2, conv3_b, x2, outp, 512,
        (long)HID * HW, (long)CCH * HW, 1);
}